// round 6
// baseline (speedup 1.0000x reference)
#include <cuda_runtime.h>
#include <math.h>

// Dynamics_79843442033036 — fused analytic grad/HVV kernel.
// Round 6: K-vectorized phase-2 (transposed [s][i] tiles, XOR-swizzled,
// zero pack-MOVs, conflict-free loads), dual-group pipelining.

typedef unsigned long long ull;

#define HID     128
#define DIMV    8
#define BATCHN  65536
#define TBS     32
#define NTILES  (BATCHN / TBS)      // 2048
#define NTHREADS 512
#define GTHREADS 256
#define GRID    152
#define NWORKERS (GRID * 2)

#define IP  128                      // [s][i] tile pitch (swizzled)
#define XP  17
#define W0P 10
#define HVP 33
#define GBP 9

// ---- shared weights (float offsets) ----
#define SM_W1   0                            // [128][128] swizzled
#define SM_W0   (SM_W1 + HID*HID)            // 16384
#define SM_W0D  (SM_W0 + HID*W0P)            // 17664
#define SM_B0   (SM_W0D + HID*DIMV*2)        // 19712
#define SM_B1   (SM_B0 + HID)
#define SM_W2   (SM_B1 + HID)
#define SM_K    (SM_W2 + HID)
#define SM_D    (SM_K + 64)
#define SM_GRPBASE (SM_D + 64)               // 20224
// ---- per-group region ----
#define G_H1    0                            // [32][128] swizzled
#define G_E1    (G_H1 + TBS*IP)              // 4096
#define G_F1    (G_E1 + TBS*IP)              // 8192
#define G_AS    (G_F1 + TBS*IP)              // 12288  [128][32] a / sbuf
#define G_X     (G_AS + HID*TBS)             // 16384  [32][17]
#define G_G     (G_X + TBS*XP)               // 16928  [32][9]
#define G_HVV   (G_G + TBS*GBP)              // 17216
#define G_HVP   (G_HVV + TBS)                // 17248
#define G_SIZE  (G_HVP + 32*HVP)             // 18304
#define SM_TOTAL (SM_GRPBASE + 2*G_SIZE)     // 56832 floats
#define SMEM_BYTES (SM_TOTAL * sizeof(float))

__device__ __forceinline__ ull pack2(float x, float y) {
    ull r; asm("mov.b64 %0, {%1,%2};" : "=l"(r) : "f"(x), "f"(y)); return r;
}
__device__ __forceinline__ float2 unpack2(ull v) {
    float2 r; asm("mov.b64 {%0,%1}, %2;" : "=f"(r.x), "=f"(r.y) : "l"(v)); return r;
}
__device__ __forceinline__ ull fma2(ull a, ull b, ull c) {
    ull r; asm("fma.rn.f32x2 %0, %1, %2, %3;" : "=l"(r) : "l"(a), "l"(b), "l"(c)); return r;
}
// fast tanh: 1 - 2/(e^{2z}+1). Correct saturation, rel err ~1e-6.
__device__ __forceinline__ float ftanh(float z) {
    float e = __expf(2.f * z);
    return 1.f - __fdividef(2.f, e + 1.f);
}

extern "C" __global__ void __launch_bounds__(NTHREADS, 1)
dyn_kernel(const float* __restrict__ X,  const float* __restrict__ Km,
           const float* __restrict__ Dm, const float* __restrict__ W0,
           const float* __restrict__ b0, const float* __restrict__ W1,
           const float* __restrict__ b1, const float* __restrict__ W2,
           float* __restrict__ out)
{
    extern __shared__ float sm[];
    float* W1s = sm + SM_W1;
    float* W0s = sm + SM_W0;
    float* W0d = sm + SM_W0D;
    float* b0s = sm + SM_B0;
    float* b1s = sm + SM_B1;
    float* w2s = sm + SM_W2;
    float* Ks  = sm + SM_K;
    float* Ds  = sm + SM_D;

    const int tid   = threadIdx.x;
    const int group = tid >> 8;
    const int gtid  = tid & 255;
    const int gbar  = group + 1;

    float* gbase = sm + SM_GRPBASE + group * G_SIZE;
    float* h1t = gbase + G_H1;
    float* e1t = gbase + G_E1;
    float* f1t = gbase + G_F1;
    float* a_s = gbase + G_AS;          // also sbuf after phase-3 barrier
    float* Xs  = gbase + G_X;
    float* gbf = gbase + G_G;
    float* hvs = gbase + G_HVV;
    float* hvp_s = gbase + G_HVP;

    // ---- one-time weight staging (whole CTA) ----
    // W1 stored [j][i] with 16B-block swizzle: blk' = (i>>2) ^ ((j>>2)&7)
    for (int idx = tid; idx < HID*HID; idx += NTHREADS) {
        int j = idx >> 7, i = idx & 127;
        int blk = (i >> 2) ^ ((j >> 2) & 7);
        W1s[j*IP + (blk << 2) + (i & 3)] = W1[idx];
    }
    for (int idx = tid; idx < HID*DIMV; idx += NTHREADS) {
        int i = idx >> 3, k = idx & 7;
        float w = W0[idx];
        W0s[i*W0P + k] = w;
        W0d[idx*2]     = w;
        W0d[idx*2 + 1] = w;
    }
    if (tid < HID) { b0s[tid] = b0[tid]; b1s[tid] = b1[tid]; w2s[tid] = W2[tid]; }
    if (tid < 64)  { Ks[tid] = Km[tid]; Ds[tid] = Dm[tid]; }
    __syncthreads();

    const int tx = gtid & 7;            // 8 sample-groups x 4 samples
    const int jy = gtid >> 3;           // 32 hidden-groups x 4 rows
    const int s0 = tx * 4;
    const int j0 = jy * 4;
    const int qf = gtid & 7;
    const int sf = gtid >> 3;

    // swizzle keys
    const int dkey  = tx;                       // data tiles: rows s0..s0+3 share s>>2 = tx
    const int kwoW  = ((tx ^ (jy & 7)) << 4);   // W byte-offset XOR key for k'-order
    const int doff  = ((jy ^ tx) << 2);         // data block offset for i-block = jy

    const int worker = blockIdx.x * 2 + group;

    for (int tile = worker; tile < NTILES; tile += NWORKERS) {
        const int base = tile * TBS;

        // ---- stage X tile ----
        for (int idx = gtid; idx < TBS*16; idx += GTHREADS) {
            int s = idx >> 4, k = idx & 15;
            Xs[s*XP + k] = X[base*16 + idx];
        }
        asm volatile("bar.sync %0, 256;" :: "r"(gbar) : "memory");

        // ---- phase 1: h1, h1', h1''  -> [s][i] swizzled, float4 over i ----
        {
            float hh[4][4], ee[4][4], ff[4][4];   // [ss][c]
            #pragma unroll
            for (int ss = 0; ss < 4; ss++) {
                const int s = s0 + ss;
                float xr[8], vr[8];
                #pragma unroll
                for (int k = 0; k < 8; k++) { xr[k] = Xs[s*XP + k]; vr[k] = Xs[s*XP + 8 + k]; }
                #pragma unroll
                for (int c = 0; c < 4; c++) {
                    const int i = j0 + c;
                    float z = b0s[i], t = 0.f;
                    #pragma unroll
                    for (int k = 0; k < 8; k++) {
                        float w = W0s[i*W0P + k];
                        z = fmaf(w, xr[k], z);
                        t = fmaf(w, vr[k], t);
                    }
                    float h = ftanh(z);
                    float d = 1.f - h*h;
                    float e = d * t;
                    float f = -2.f * h * t * e;
                    hh[ss][c] = h; ee[ss][c] = e; ff[ss][c] = f;
                }
            }
            #pragma unroll
            for (int ss = 0; ss < 4; ss++) {
                const int off = (s0 + ss)*IP + doff;
                *(float4*)(h1t + off) = make_float4(hh[ss][0],hh[ss][1],hh[ss][2],hh[ss][3]);
                *(float4*)(e1t + off) = make_float4(ee[ss][0],ee[ss][1],ee[ss][2],ee[ss][3]);
                *(float4*)(f1t + off) = make_float4(ff[ss][0],ff[ss][1],ff[ss][2],ff[ss][3]);
            }
        }
        asm volatile("bar.sync %0, 256;" :: "r"(gbar) : "memory");

        // ---- phase 2: K-vectorized f32x2 matvecs, two passes (z then P) ----
        const char* W1j0 = (const char*)(W1s + j0*IP);
        const char* hB0 = (const char*)(h1t + (s0+0)*IP);
        const char* hB1 = (const char*)(h1t + (s0+1)*IP);
        const char* hB2 = (const char*)(h1t + (s0+2)*IP);
        const char* hB3 = (const char*)(h1t + (s0+3)*IP);

        float z2r[4][4], ppr[4][4];   // [c][ss]

        #pragma unroll
        for (int pass = 0; pass < 2; pass++) {
            const char* dB0 = pass ? (const char*)(e1t + (s0+0)*IP) : hB0;
            const char* dB1 = pass ? (const char*)(e1t + (s0+1)*IP) : hB1;
            const char* dB2 = pass ? (const char*)(e1t + (s0+2)*IP) : hB2;
            const char* dB3 = pass ? (const char*)(e1t + (s0+3)*IP) : hB3;
            ull acc[4][4];
            #pragma unroll
            for (int c = 0; c < 4; c++)
                #pragma unroll
                for (int ss = 0; ss < 4; ss++) acc[c][ss] = 0ull;

            #pragma unroll 4
            for (int kp = 0; kp < 32; kp++) {
                const int wo = (kp << 4) ^ kwoW;
                const char* wB = W1j0 + wo;
                const ulonglong2 wv0 = *(const ulonglong2*)(wB);
                const ulonglong2 wv1 = *(const ulonglong2*)(wB + 512);
                const ulonglong2 wv2 = *(const ulonglong2*)(wB + 1024);
                const ulonglong2 wv3 = *(const ulonglong2*)(wB + 1536);
                const ulonglong2 d0 = *(const ulonglong2*)(dB0 + (kp<<4));
                const ulonglong2 d1 = *(const ulonglong2*)(dB1 + (kp<<4));
                const ulonglong2 d2 = *(const ulonglong2*)(dB2 + (kp<<4));
                const ulonglong2 d3 = *(const ulonglong2*)(dB3 + (kp<<4));
                acc[0][0]=fma2(wv0.x,d0.x,acc[0][0]); acc[0][0]=fma2(wv0.y,d0.y,acc[0][0]);
                acc[0][1]=fma2(wv0.x,d1.x,acc[0][1]); acc[0][1]=fma2(wv0.y,d1.y,acc[0][1]);
                acc[0][2]=fma2(wv0.x,d2.x,acc[0][2]); acc[0][2]=fma2(wv0.y,d2.y,acc[0][2]);
                acc[0][3]=fma2(wv0.x,d3.x,acc[0][3]); acc[0][3]=fma2(wv0.y,d3.y,acc[0][3]);
                acc[1][0]=fma2(wv1.x,d0.x,acc[1][0]); acc[1][0]=fma2(wv1.y,d0.y,acc[1][0]);
                acc[1][1]=fma2(wv1.x,d1.x,acc[1][1]); acc[1][1]=fma2(wv1.y,d1.y,acc[1][1]);
                acc[1][2]=fma2(wv1.x,d2.x,acc[1][2]); acc[1][2]=fma2(wv1.y,d2.y,acc[1][2]);
                acc[1][3]=fma2(wv1.x,d3.x,acc[1][3]); acc[1][3]=fma2(wv1.y,d3.y,acc[1][3]);
                acc[2][0]=fma2(wv2.x,d0.x,acc[2][0]); acc[2][0]=fma2(wv2.y,d0.y,acc[2][0]);
                acc[2][1]=fma2(wv2.x,d1.x,acc[2][1]); acc[2][1]=fma2(wv2.y,d1.y,acc[2][1]);
                acc[2][2]=fma2(wv2.x,d2.x,acc[2][2]); acc[2][2]=fma2(wv2.y,d2.y,acc[2][2]);
                acc[2][3]=fma2(wv2.x,d3.x,acc[2][3]); acc[2][3]=fma2(wv2.y,d3.y,acc[2][3]);
                acc[3][0]=fma2(wv3.x,d0.x,acc[3][0]); acc[3][0]=fma2(wv3.y,d0.y,acc[3][0]);
                acc[3][1]=fma2(wv3.x,d1.x,acc[3][1]); acc[3][1]=fma2(wv3.y,d1.y,acc[3][1]);
                acc[3][2]=fma2(wv3.x,d2.x,acc[3][2]); acc[3][2]=fma2(wv3.y,d2.y,acc[3][2]);
                acc[3][3]=fma2(wv3.x,d3.x,acc[3][3]); acc[3][3]=fma2(wv3.y,d3.y,acc[3][3]);
            }
            #pragma unroll
            for (int c = 0; c < 4; c++)
                #pragma unroll
                for (int ss = 0; ss < 4; ss++) {
                    float2 t = unpack2(acc[c][ss]);
                    if (pass == 0) z2r[c][ss] = t.x + t.y;
                    else           ppr[c][ss] = t.x + t.y;
                }
        }
        // (no barrier needed: a_s is a separate buffer)

        // ---- phase-2 epilogue: a = d2*w2 -> a_s[j][s]; P-term hvv in regs ----
        float hvp[4] = {0.f, 0.f, 0.f, 0.f};
        #pragma unroll
        for (int c = 0; c < 4; c++) {
            const int j = j0 + c;
            const float w2j = w2s[j];
            const float bj  = b1s[j];
            float av[4];
            #pragma unroll
            for (int ss = 0; ss < 4; ss++) {
                float h2 = ftanh(z2r[c][ss] + bj);
                float d2 = 1.f - h2*h2;
                float P = ppr[c][ss];
                hvp[ss] = fmaf(-2.f*w2j, h2*d2*P*P, hvp[ss]);
                av[ss] = d2 * w2j;
            }
            *(float4*)(a_s + j*TBS + s0) = make_float4(av[0],av[1],av[2],av[3]);
        }
        asm volatile("bar.sync %0, 256;" :: "r"(gbar) : "memory");  // a ready

        // ---- phase 3: U = W1^T a  (f32x2, sample-packed) ----
        ull au2[4][2];
        #pragma unroll
        for (int c = 0; c < 4; c++) { au2[c][0]=0ull; au2[c][1]=0ull; }
        {
            const float* apnt = a_s + s0;
            #pragma unroll 2
            for (int jb = 0; jb < 32; jb++) {
                const int woff = ((jy ^ (jb & 7)) << 4);
                const char* wB = (const char*)W1s + jb*2048 + woff;
                #pragma unroll
                for (int cc = 0; cc < 4; cc++) {
                    const int j = 4*jb + cc;
                    const ulonglong2 av = *(const ulonglong2*)(apnt + j*TBS);
                    const float4 wv = *(const float4*)(wB + cc*512);
                    const float* wa = (const float*)&wv;
                    ull w;
                    w = pack2(wa[0], wa[0]);
                    au2[0][0]=fma2(w,av.x,au2[0][0]); au2[0][1]=fma2(w,av.y,au2[0][1]);
                    w = pack2(wa[1], wa[1]);
                    au2[1][0]=fma2(w,av.x,au2[1][0]); au2[1][1]=fma2(w,av.y,au2[1][1]);
                    w = pack2(wa[2], wa[2]);
                    au2[2][0]=fma2(w,av.x,au2[2][0]); au2[2][1]=fma2(w,av.y,au2[2][1]);
                    w = pack2(wa[3], wa[3]);
                    au2[3][0]=fma2(w,av.x,au2[3][0]); au2[3][1]=fma2(w,av.y,au2[3][1]);
                }
            }
        }
        asm volatile("bar.sync %0, 256;" :: "r"(gbar) : "memory");  // a_s reads done

        // ---- phase-3 epilogue: hvv += U.h1'' ; sbuf(=a_s) = d1*U ----
        {
            float uu[4][4];   // [c][ss]
            #pragma unroll
            for (int c = 0; c < 4; c++) {
                float2 a = unpack2(au2[c][0]), b = unpack2(au2[c][1]);
                uu[c][0]=a.x; uu[c][1]=a.y; uu[c][2]=b.x; uu[c][3]=b.y;
            }
            float sv[4][4];   // [c][ss]
            #pragma unroll
            for (int ss = 0; ss < 4; ss++) {
                const int off = (s0 + ss)*IP + doff;
                const float4 hv = *(const float4*)(h1t + off);
                const float4 fv = *(const float4*)(f1t + off);
                const float hh4[4] = {hv.x, hv.y, hv.z, hv.w};
                const float fpp[4] = {fv.x, fv.y, fv.z, fv.w};
                #pragma unroll
                for (int c = 0; c < 4; c++) {
                    hvp[ss] = fmaf(uu[c][ss], fpp[c], hvp[ss]);
                    sv[c][ss] = (1.f - hh4[c]*hh4[c]) * uu[c][ss];
                }
            }
            #pragma unroll
            for (int c = 0; c < 4; c++)
                *(float4*)(a_s + (j0+c)*TBS + s0) =
                    make_float4(sv[c][0],sv[c][1],sv[c][2],sv[c][3]);
            #pragma unroll
            for (int ss = 0; ss < 4; ss++)
                hvp_s[jy*HVP + s0 + ss] = hvp[ss];
        }
        asm volatile("bar.sync %0, 256;" :: "r"(gbar) : "memory");

        // ---- phase 4 (warps 0-3): g = W0^T sbuf  ||  hvv reduce (warp 4) ----
        if (gtid < 128) {
            const int q  = gtid & 7;
            const int sp = gtid >> 3;
            ull acc = 0ull;
            const ull* w0dp = (const ull*)(W0d) + q;
            const float* fp = a_s + 2*sp;
            #pragma unroll 4
            for (int i = 0; i < HID; i++)
                acc = fma2(w0dp[i*8], *(const ull*)(fp + i*TBS), acc);
            float2 gv = unpack2(acc);
            gbf[(2*sp)*GBP + q]   = gv.x;
            gbf[(2*sp+1)*GBP + q] = gv.y;
        } else if (gtid < 160) {
            const int s = gtid - 128;
            float acc = 0.f;
            #pragma unroll
            for (int g = 0; g < 32; g++) acc += hvp_s[g*HVP + s];
            hvs[s] = acc;
        }
        asm volatile("bar.sync %0, 256;" :: "r"(gbar) : "memory");

        // ---- phase 5: Sherman-Morrison combine + coalesced store ----
        {
            float g[8];
            #pragma unroll
            for (int k = 0; k < 8; k++) g[k] = gbf[sf*GBP + k];
            float gg = 0.f;
            #pragma unroll
            for (int k = 0; k < 8; k++) gg = fmaf(g[k], g[k], gg);
            float xr[8], vr[8];
            #pragma unroll
            for (int k = 0; k < 8; k++) { xr[k] = Xs[sf*XP + k]; vr[k] = Xs[sf*XP + 8 + k]; }
            float gf = 0.f, fq = 0.f;
            #pragma unroll
            for (int q2 = 0; q2 < 8; q2++) {
                float fo = 0.f;
                #pragma unroll
                for (int k = 0; k < 8; k++) {
                    fo = fmaf(-Ds[q2*8+k], vr[k], fo);
                    fo = fmaf(-Ks[q2*8+k], xr[k], fo);
                }
                gf = fmaf(g[q2], fo, gf);
                if (q2 == qf) fq = fo;
            }
            float scale = (gf + hvs[sf]) / (1.f + gg);
            out[(base + sf)*8 + qf] = fq - g[qf]*scale;
        }
        asm volatile("bar.sync %0, 256;" :: "r"(gbar) : "memory");
    }
}

extern "C" void kernel_launch(void* const* d_in, const int* in_sizes, int n_in,
                              void* d_out, int out_size)
{
    const float* X  = (const float*)d_in[0];
    const float* Km = (const float*)d_in[1];
    const float* Dm = (const float*)d_in[2];
    const float* W0 = (const float*)d_in[3];
    const float* b0 = (const float*)d_in[4];
    const float* W1 = (const float*)d_in[5];
    const float* b1 = (const float*)d_in[6];
    const float* W2 = (const float*)d_in[7];

    cudaFuncSetAttribute(dyn_kernel, cudaFuncAttributeMaxDynamicSharedMemorySize,
                         (int)SMEM_BYTES);
    dyn_kernel<<<GRID, NTHREADS, SMEM_BYTES>>>(X, Km, Dm, W0, b0, W1, b1, W2,
                                               (float*)d_out);
}

// round 7
// speedup vs baseline: 3.2899x; 3.2899x over previous
#include <cuda_runtime.h>
#include <math.h>

// Dynamics_79843442033036 — fused analytic grad/HVV kernel.
// Round 7: round-6 K-vectorized phase-2 with the bank-conflict bug fixed:
// iterate LOGICAL blocks in lockstep; each lane XORs its own swizzle key
// (tx for data tiles, jy for W rows) so physical addresses spread banks.

typedef unsigned long long ull;

#define HID     128
#define DIMV    8
#define BATCHN  65536
#define TBS     32
#define NTILES  (BATCHN / TBS)      // 2048
#define NTHREADS 512
#define GTHREADS 256
#define GRID    152
#define NWORKERS (GRID * 2)

#define IP  128                      // [s][i] tile pitch (swizzled blocks)
#define XP  17
#define W0P 10
#define HVP 33
#define GBP 9

// ---- shared weights (float offsets) ----
#define SM_W1   0                            // [128][128] block-swizzled
#define SM_W0   (SM_W1 + HID*HID)            // 16384
#define SM_W0D  (SM_W0 + HID*W0P)            // 17664
#define SM_B0   (SM_W0D + HID*DIMV*2)        // 19712
#define SM_B1   (SM_B0 + HID)
#define SM_W2   (SM_B1 + HID)
#define SM_K    (SM_W2 + HID)
#define SM_D    (SM_K + 64)
#define SM_GRPBASE (SM_D + 64)               // 20224
// ---- per-group region ----
#define G_H1    0                            // [32][128] block-swizzled
#define G_E1    (G_H1 + TBS*IP)              // 4096
#define G_F1    (G_E1 + TBS*IP)              // 8192
#define G_AS    (G_F1 + TBS*IP)              // 12288  [128][32] a / sbuf
#define G_X     (G_AS + HID*TBS)             // 16384  [32][17]
#define G_G     (G_X + TBS*XP)               // 16928  [32][9]
#define G_HVV   (G_G + TBS*GBP)              // 17216
#define G_HVP   (G_HVV + TBS)                // 17248
#define G_SIZE  (G_HVP + 32*HVP)             // 18304
#define SM_TOTAL (SM_GRPBASE + 2*G_SIZE)     // 56832 floats
#define SMEM_BYTES (SM_TOTAL * sizeof(float))

__device__ __forceinline__ ull pack2(float x, float y) {
    ull r; asm("mov.b64 %0, {%1,%2};" : "=l"(r) : "f"(x), "f"(y)); return r;
}
__device__ __forceinline__ float2 unpack2(ull v) {
    float2 r; asm("mov.b64 {%0,%1}, %2;" : "=f"(r.x), "=f"(r.y) : "l"(v)); return r;
}
__device__ __forceinline__ ull fma2(ull a, ull b, ull c) {
    ull r; asm("fma.rn.f32x2 %0, %1, %2, %3;" : "=l"(r) : "l"(a), "l"(b), "l"(c)); return r;
}
// fast tanh: 1 - 2/(e^{2z}+1). Correct saturation, rel err ~1e-6.
__device__ __forceinline__ float ftanh(float z) {
    float e = __expf(2.f * z);
    return 1.f - __fdividef(2.f, e + 1.f);
}

extern "C" __global__ void __launch_bounds__(NTHREADS, 1)
dyn_kernel(const float* __restrict__ X,  const float* __restrict__ Km,
           const float* __restrict__ Dm, const float* __restrict__ W0,
           const float* __restrict__ b0, const float* __restrict__ W1,
           const float* __restrict__ b1, const float* __restrict__ W2,
           float* __restrict__ out)
{
    extern __shared__ float sm[];
    float* W1s = sm + SM_W1;
    float* W0s = sm + SM_W0;
    float* W0d = sm + SM_W0D;
    float* b0s = sm + SM_B0;
    float* b1s = sm + SM_B1;
    float* w2s = sm + SM_W2;
    float* Ks  = sm + SM_K;
    float* Ds  = sm + SM_D;

    const int tid   = threadIdx.x;
    const int group = tid >> 8;
    const int gtid  = tid & 255;
    const int gbar  = group + 1;

    float* gbase = sm + SM_GRPBASE + group * G_SIZE;
    float* h1t = gbase + G_H1;
    float* e1t = gbase + G_E1;
    float* f1t = gbase + G_F1;
    float* a_s = gbase + G_AS;          // also sbuf after phase-3 barrier
    float* Xs  = gbase + G_X;
    float* gbf = gbase + G_G;
    float* hvs = gbase + G_HVV;
    float* hvp_s = gbase + G_HVP;

    // ---- one-time weight staging (whole CTA) ----
    // W1 stored [j][i], 16B-block swizzle: physical_blk = (i>>2) ^ ((j>>2)&7)
    for (int idx = tid; idx < HID*HID; idx += NTHREADS) {
        int j = idx >> 7, i = idx & 127;
        int blk = (i >> 2) ^ ((j >> 2) & 7);
        W1s[j*IP + (blk << 2) + (i & 3)] = W1[idx];
    }
    for (int idx = tid; idx < HID*DIMV; idx += NTHREADS) {
        int i = idx >> 3, k = idx & 7;
        float w = W0[idx];
        W0s[i*W0P + k] = w;
        W0d[idx*2]     = w;
        W0d[idx*2 + 1] = w;
    }
    if (tid < HID) { b0s[tid] = b0[tid]; b1s[tid] = b1[tid]; w2s[tid] = W2[tid]; }
    if (tid < 64)  { Ks[tid] = Km[tid]; Ds[tid] = Dm[tid]; }
    __syncthreads();

    const int tx = gtid & 7;            // 8 sample-groups x 4 samples
    const int jy = gtid >> 3;           // 32 hidden-groups x 4 rows
    const int s0 = tx * 4;
    const int j0 = jy * 4;
    const int qf = gtid & 7;
    const int sf = gtid >> 3;

    // swizzle keys (byte offsets for 16B blocks)
    const int txkey = tx << 4;                  // data tiles: row owner key = s>>2 = tx
    const int wkey  = (jy & 7) << 4;            // W rows j0..j0+3: key = (j>>2)&7 = jy&7
    const int doff  = ((jy ^ tx) << 2);         // phase-1/3-epilogue: logical blk jy at row s

    const int worker = blockIdx.x * 2 + group;

    for (int tile = worker; tile < NTILES; tile += NWORKERS) {
        const int base = tile * TBS;

        // ---- stage X tile ----
        for (int idx = gtid; idx < TBS*16; idx += GTHREADS) {
            int s = idx >> 4, k = idx & 15;
            Xs[s*XP + k] = X[base*16 + idx];
        }
        asm volatile("bar.sync %0, 256;" :: "r"(gbar) : "memory");

        // ---- phase 1: h1, h1', h1''  -> [s][i] swizzled, float4 over i ----
        {
            float hh[4][4], ee[4][4], ff[4][4];   // [ss][c]
            #pragma unroll
            for (int ss = 0; ss < 4; ss++) {
                const int s = s0 + ss;
                float xr[8], vr[8];
                #pragma unroll
                for (int k = 0; k < 8; k++) { xr[k] = Xs[s*XP + k]; vr[k] = Xs[s*XP + 8 + k]; }
                #pragma unroll
                for (int c = 0; c < 4; c++) {
                    const int i = j0 + c;
                    float z = b0s[i], t = 0.f;
                    #pragma unroll
                    for (int k = 0; k < 8; k++) {
                        float w = W0s[i*W0P + k];
                        z = fmaf(w, xr[k], z);
                        t = fmaf(w, vr[k], t);
                    }
                    float h = ftanh(z);
                    float d = 1.f - h*h;
                    float e = d * t;
                    float f = -2.f * h * t * e;
                    hh[ss][c] = h; ee[ss][c] = e; ff[ss][c] = f;
                }
            }
            #pragma unroll
            for (int ss = 0; ss < 4; ss++) {
                const int off = (s0 + ss)*IP + doff;
                *(float4*)(h1t + off) = make_float4(hh[ss][0],hh[ss][1],hh[ss][2],hh[ss][3]);
                *(float4*)(e1t + off) = make_float4(ee[ss][0],ee[ss][1],ee[ss][2],ee[ss][3]);
                *(float4*)(f1t + off) = make_float4(ff[ss][0],ff[ss][1],ff[ss][2],ff[ss][3]);
            }
        }
        asm volatile("bar.sync %0, 256;" :: "r"(gbar) : "memory");

        // ---- phase 2: K-vectorized f32x2 matvecs, two passes (z then P) ----
        // Logical block kp in lockstep; physical = kp ^ key per lane.
        const char* W1j0 = (const char*)(W1s + j0*IP);
        const char* hB0 = (const char*)(h1t + (s0+0)*IP);
        const char* hB1 = (const char*)(h1t + (s0+1)*IP);
        const char* hB2 = (const char*)(h1t + (s0+2)*IP);
        const char* hB3 = (const char*)(h1t + (s0+3)*IP);

        float z2r[4][4], ppr[4][4];   // [c][ss]

        #pragma unroll
        for (int pass = 0; pass < 2; pass++) {
            const char* dB0 = pass ? (const char*)(e1t + (s0+0)*IP) : hB0;
            const char* dB1 = pass ? (const char*)(e1t + (s0+1)*IP) : hB1;
            const char* dB2 = pass ? (const char*)(e1t + (s0+2)*IP) : hB2;
            const char* dB3 = pass ? (const char*)(e1t + (s0+3)*IP) : hB3;
            ull acc[4][4];
            #pragma unroll
            for (int c = 0; c < 4; c++)
                #pragma unroll
                for (int ss = 0; ss < 4; ss++) acc[c][ss] = 0ull;

            #pragma unroll 4
            for (int kp = 0; kp < 32; kp++) {
                const int wo   = (kp << 4) ^ wkey;    // W physical block offset
                const int dofs = (kp << 4) ^ txkey;   // data physical block offset
                const char* wB = W1j0 + wo;
                const ulonglong2 wv0 = *(const ulonglong2*)(wB);
                const ulonglong2 wv1 = *(const ulonglong2*)(wB + 512);
                const ulonglong2 wv2 = *(const ulonglong2*)(wB + 1024);
                const ulonglong2 wv3 = *(const ulonglong2*)(wB + 1536);
                const ulonglong2 d0 = *(const ulonglong2*)(dB0 + dofs);
                const ulonglong2 d1 = *(const ulonglong2*)(dB1 + dofs);
                const ulonglong2 d2 = *(const ulonglong2*)(dB2 + dofs);
                const ulonglong2 d3 = *(const ulonglong2*)(dB3 + dofs);
                acc[0][0]=fma2(wv0.x,d0.x,acc[0][0]); acc[0][0]=fma2(wv0.y,d0.y,acc[0][0]);
                acc[0][1]=fma2(wv0.x,d1.x,acc[0][1]); acc[0][1]=fma2(wv0.y,d1.y,acc[0][1]);
                acc[0][2]=fma2(wv0.x,d2.x,acc[0][2]); acc[0][2]=fma2(wv0.y,d2.y,acc[0][2]);
                acc[0][3]=fma2(wv0.x,d3.x,acc[0][3]); acc[0][3]=fma2(wv0.y,d3.y,acc[0][3]);
                acc[1][0]=fma2(wv1.x,d0.x,acc[1][0]); acc[1][0]=fma2(wv1.y,d0.y,acc[1][0]);
                acc[1][1]=fma2(wv1.x,d1.x,acc[1][1]); acc[1][1]=fma2(wv1.y,d1.y,acc[1][1]);
                acc[1][2]=fma2(wv1.x,d2.x,acc[1][2]); acc[1][2]=fma2(wv1.y,d2.y,acc[1][2]);
                acc[1][3]=fma2(wv1.x,d3.x,acc[1][3]); acc[1][3]=fma2(wv1.y,d3.y,acc[1][3]);
                acc[2][0]=fma2(wv2.x,d0.x,acc[2][0]); acc[2][0]=fma2(wv2.y,d0.y,acc[2][0]);
                acc[2][1]=fma2(wv2.x,d1.x,acc[2][1]); acc[2][1]=fma2(wv2.y,d1.y,acc[2][1]);
                acc[2][2]=fma2(wv2.x,d2.x,acc[2][2]); acc[2][2]=fma2(wv2.y,d2.y,acc[2][2]);
                acc[2][3]=fma2(wv2.x,d3.x,acc[2][3]); acc[2][3]=fma2(wv2.y,d3.y,acc[2][3]);
                acc[3][0]=fma2(wv3.x,d0.x,acc[3][0]); acc[3][0]=fma2(wv3.y,d0.y,acc[3][0]);
                acc[3][1]=fma2(wv3.x,d1.x,acc[3][1]); acc[3][1]=fma2(wv3.y,d1.y,acc[3][1]);
                acc[3][2]=fma2(wv3.x,d2.x,acc[3][2]); acc[3][2]=fma2(wv3.y,d2.y,acc[3][2]);
                acc[3][3]=fma2(wv3.x,d3.x,acc[3][3]); acc[3][3]=fma2(wv3.y,d3.y,acc[3][3]);
            }
            #pragma unroll
            for (int c = 0; c < 4; c++)
                #pragma unroll
                for (int ss = 0; ss < 4; ss++) {
                    float2 t = unpack2(acc[c][ss]);
                    if (pass == 0) z2r[c][ss] = t.x + t.y;
                    else           ppr[c][ss] = t.x + t.y;
                }
        }
        // (no barrier needed: a_s is a separate buffer)

        // ---- phase-2 epilogue: a = d2*w2 -> a_s[j][s]; P-term hvv in regs ----
        float hvp[4] = {0.f, 0.f, 0.f, 0.f};
        #pragma unroll
        for (int c = 0; c < 4; c++) {
            const int j = j0 + c;
            const float w2j = w2s[j];
            const float bj  = b1s[j];
            float av[4];
            #pragma unroll
            for (int ss = 0; ss < 4; ss++) {
                float h2 = ftanh(z2r[c][ss] + bj);
                float d2 = 1.f - h2*h2;
                float P = ppr[c][ss];
                hvp[ss] = fmaf(-2.f*w2j, h2*d2*P*P, hvp[ss]);
                av[ss] = d2 * w2j;
            }
            *(float4*)(a_s + j*TBS + s0) = make_float4(av[0],av[1],av[2],av[3]);
        }
        asm volatile("bar.sync %0, 256;" :: "r"(gbar) : "memory");  // a ready

        // ---- phase 3: U = W1^T a  (f32x2, sample-packed) ----
        ull au2[4][2];
        #pragma unroll
        for (int c = 0; c < 4; c++) { au2[c][0]=0ull; au2[c][1]=0ull; }
        {
            const float* apnt = a_s + s0;
            #pragma unroll 2
            for (int jb = 0; jb < 32; jb++) {
                const int woff = ((jy ^ (jb & 7)) << 4);
                const char* wB = (const char*)W1s + jb*2048 + woff;
                #pragma unroll
                for (int cc = 0; cc < 4; cc++) {
                    const int j = 4*jb + cc;
                    const ulonglong2 av = *(const ulonglong2*)(apnt + j*TBS);
                    const float4 wv = *(const float4*)(wB + cc*512);
                    const float* wa = (const float*)&wv;
                    ull w;
                    w = pack2(wa[0], wa[0]);
                    au2[0][0]=fma2(w,av.x,au2[0][0]); au2[0][1]=fma2(w,av.y,au2[0][1]);
                    w = pack2(wa[1], wa[1]);
                    au2[1][0]=fma2(w,av.x,au2[1][0]); au2[1][1]=fma2(w,av.y,au2[1][1]);
                    w = pack2(wa[2], wa[2]);
                    au2[2][0]=fma2(w,av.x,au2[2][0]); au2[2][1]=fma2(w,av.y,au2[2][1]);
                    w = pack2(wa[3], wa[3]);
                    au2[3][0]=fma2(w,av.x,au2[3][0]); au2[3][1]=fma2(w,av.y,au2[3][1]);
                }
            }
        }
        asm volatile("bar.sync %0, 256;" :: "r"(gbar) : "memory");  // a_s reads done

        // ---- phase-3 epilogue: hvv += U.h1'' ; sbuf(=a_s) = d1*U ----
        {
            float uu[4][4];   // [c][ss]
            #pragma unroll
            for (int c = 0; c < 4; c++) {
                float2 a = unpack2(au2[c][0]), b = unpack2(au2[c][1]);
                uu[c][0]=a.x; uu[c][1]=a.y; uu[c][2]=b.x; uu[c][3]=b.y;
            }
            float sv[4][4];   // [c][ss]
            #pragma unroll
            for (int ss = 0; ss < 4; ss++) {
                const int off = (s0 + ss)*IP + doff;
                const float4 hv = *(const float4*)(h1t + off);
                const float4 fv = *(const float4*)(f1t + off);
                const float hh4[4] = {hv.x, hv.y, hv.z, hv.w};
                const float fpp[4] = {fv.x, fv.y, fv.z, fv.w};
                #pragma unroll
                for (int c = 0; c < 4; c++) {
                    hvp[ss] = fmaf(uu[c][ss], fpp[c], hvp[ss]);
                    sv[c][ss] = (1.f - hh4[c]*hh4[c]) * uu[c][ss];
                }
            }
            #pragma unroll
            for (int c = 0; c < 4; c++)
                *(float4*)(a_s + (j0+c)*TBS + s0) =
                    make_float4(sv[c][0],sv[c][1],sv[c][2],sv[c][3]);
            #pragma unroll
            for (int ss = 0; ss < 4; ss++)
                hvp_s[jy*HVP + s0 + ss] = hvp[ss];
        }
        asm volatile("bar.sync %0, 256;" :: "r"(gbar) : "memory");

        // ---- phase 4 (warps 0-3): g = W0^T sbuf  ||  hvv reduce (warp 4) ----
        if (gtid < 128) {
            const int q  = gtid & 7;
            const int sp = gtid >> 3;
            ull acc = 0ull;
            const ull* w0dp = (const ull*)(W0d) + q;
            const float* fp = a_s + 2*sp;
            #pragma unroll 4
            for (int i = 0; i < HID; i++)
                acc = fma2(w0dp[i*8], *(const ull*)(fp + i*TBS), acc);
            float2 gv = unpack2(acc);
            gbf[(2*sp)*GBP + q]   = gv.x;
            gbf[(2*sp+1)*GBP + q] = gv.y;
        } else if (gtid < 160) {
            const int s = gtid - 128;
            float acc = 0.f;
            #pragma unroll
            for (int g = 0; g < 32; g++) acc += hvp_s[g*HVP + s];
            hvs[s] = acc;
        }
        asm volatile("bar.sync %0, 256;" :: "r"(gbar) : "memory");

        // ---- phase 5: Sherman-Morrison combine + coalesced store ----
        {
            float g[8];
            #pragma unroll
            for (int k = 0; k < 8; k++) g[k] = gbf[sf*GBP + k];
            float gg = 0.f;
            #pragma unroll
            for (int k = 0; k < 8; k++) gg = fmaf(g[k], g[k], gg);
            float xr[8], vr[8];
            #pragma unroll
            for (int k = 0; k < 8; k++) { xr[k] = Xs[sf*XP + k]; vr[k] = Xs[sf*XP + 8 + k]; }
            float gf = 0.f, fq = 0.f;
            #pragma unroll
            for (int q2 = 0; q2 < 8; q2++) {
                float fo = 0.f;
                #pragma unroll
                for (int k = 0; k < 8; k++) {
                    fo = fmaf(-Ds[q2*8+k], vr[k], fo);
                    fo = fmaf(-Ks[q2*8+k], xr[k], fo);
                }
                gf = fmaf(g[q2], fo, gf);
                if (q2 == qf) fq = fo;
            }
            float scale = (gf + hvs[sf]) / (1.f + gg);
            out[(base + sf)*8 + qf] = fq - g[qf]*scale;
        }
        asm volatile("bar.sync %0, 256;" :: "r"(gbar) : "memory");
    }
}

extern "C" void kernel_launch(void* const* d_in, const int* in_sizes, int n_in,
                              void* d_out, int out_size)
{
    const float* X  = (const float*)d_in[0];
    const float* Km = (const float*)d_in[1];
    const float* Dm = (const float*)d_in[2];
    const float* W0 = (const float*)d_in[3];
    const float* b0 = (const float*)d_in[4];
    const float* W1 = (const float*)d_in[5];
    const float* b1 = (const float*)d_in[6];
    const float* W2 = (const float*)d_in[7];

    cudaFuncSetAttribute(dyn_kernel, cudaFuncAttributeMaxDynamicSharedMemorySize,
                         (int)SMEM_BYTES);
    dyn_kernel<<<GRID, NTHREADS, SMEM_BYTES>>>(X, Km, Dm, W0, b0, W1, b1, W2,
                                               (float*)d_out);
}

// round 8
// speedup vs baseline: 3.3209x; 1.0094x over previous
#include <cuda_runtime.h>
#include <math.h>

// Dynamics_79843442033036 — fused analytic grad/HVV kernel.
// Round 8 = round-5 structure (best measured) with barrier count 7->4/tile:
// separate a_s buffer, double-buffered X with LDG prefetch, no trailing barrier.

typedef unsigned long long ull;

#define HID     128
#define DIMV    8
#define BATCHN  65536
#define TBS     32
#define NTILES  (BATCHN / TBS)      // 2048
#define NTHREADS 512
#define GTHREADS 256
#define GRID    152
#define NWORKERS (GRID * 2)

#define W1P 128
#define XP  17
#define HVP 33
#define GBP 9

// ---- shared weights (float offsets) ----
#define SM_W1   0                            // [128][128]
#define SM_W0D  (SM_W1 + HID*HID)            // 16384 (dup pairs, 2048)
#define SM_B0   (SM_W0D + HID*DIMV*2)        // 18432
#define SM_B1   (SM_B0 + HID)
#define SM_W2   (SM_B1 + HID)
#define SM_K    (SM_W2 + HID)
#define SM_D    (SM_K + 64)
#define SM_GRPBASE (SM_D + 64)               // 18944
// ---- per-group region ----
#define G_H1    0                            // [128][32]
#define G_E1    (G_H1 + HID*TBS)             // 4096
#define G_F1    (G_E1 + HID*TBS)             // 8192
#define G_AS    (G_F1 + HID*TBS)             // 12288 [128][32]
#define G_X     (G_AS + HID*TBS)             // 16384 2 x [32][17]
#define G_G     (G_X + 2*TBS*XP)             // 17472 [32][9]
#define G_HVV   (G_G + TBS*GBP)              // 17760
#define G_HVP   (G_HVV + TBS)                // 17792 [32][33]
#define G_SIZE  (G_HVP + 32*HVP)             // 18848
#define SM_TOTAL (SM_GRPBASE + 2*G_SIZE)     // 56640 floats = 221.3 KB
#define SMEM_BYTES (SM_TOTAL * sizeof(float))

__device__ __forceinline__ ull pack2(float x, float y) {
    ull r; asm("mov.b64 %0, {%1,%2};" : "=l"(r) : "f"(x), "f"(y)); return r;
}
__device__ __forceinline__ float2 unpack2(ull v) {
    float2 r; asm("mov.b64 {%0,%1}, %2;" : "=f"(r.x), "=f"(r.y) : "l"(v)); return r;
}
__device__ __forceinline__ ull fma2(ull a, ull b, ull c) {
    ull r; asm("fma.rn.f32x2 %0, %1, %2, %3;" : "=l"(r) : "l"(a), "l"(b), "l"(c)); return r;
}
// fast tanh: 1 - 2/(e^{2z}+1). Correct saturation, rel err ~1e-6.
__device__ __forceinline__ float ftanh(float z) {
    float e = __expf(2.f * z);
    return 1.f - __fdividef(2.f, e + 1.f);
}

extern "C" __global__ void __launch_bounds__(NTHREADS, 1)
dyn_kernel(const float* __restrict__ X,  const float* __restrict__ Km,
           const float* __restrict__ Dm, const float* __restrict__ W0,
           const float* __restrict__ b0, const float* __restrict__ W1,
           const float* __restrict__ b1, const float* __restrict__ W2,
           float* __restrict__ out)
{
    extern __shared__ float sm[];
    float* W1s = sm + SM_W1;
    float* W0d = sm + SM_W0D;
    float* b0s = sm + SM_B0;
    float* b1s = sm + SM_B1;
    float* w2s = sm + SM_W2;
    float* Ks  = sm + SM_K;
    float* Ds  = sm + SM_D;

    const int tid   = threadIdx.x;
    const int group = tid >> 8;
    const int gtid  = tid & 255;
    const int gbar  = group + 1;

    float* gbase = sm + SM_GRPBASE + group * G_SIZE;
    float* h1s = gbase + G_H1;
    float* e1s = gbase + G_E1;
    float* f1s = gbase + G_F1;    // h1'' then sbuf
    float* a_s = gbase + G_AS;
    float* Xq  = gbase + G_X;     // two buffers of 544
    float* gbf = gbase + G_G;
    float* hvs = gbase + G_HVV;
    float* hvp_s = gbase + G_HVP;

    // ---- one-time weight staging (whole CTA) ----
    for (int idx = tid * 4; idx < HID*HID; idx += NTHREADS * 4)
        *(float4*)(W1s + idx) = *(const float4*)(W1 + idx);
    for (int idx = tid; idx < HID*DIMV; idx += NTHREADS) {
        float w = W0[idx];
        W0d[idx*2]     = w;
        W0d[idx*2 + 1] = w;
    }
    if (tid < HID) { b0s[tid] = b0[tid]; b1s[tid] = b1[tid]; w2s[tid] = W2[tid]; }
    if (tid < 64)  { Ks[tid] = Km[tid]; Ds[tid] = Dm[tid]; }
    __syncthreads();

    const int tx = gtid & 7;            // 8 sample-groups x 4 samples
    const int jy = gtid >> 3;           // 32 hidden-groups x 4 rows
    const int s0 = tx * 4;
    const int j0 = jy * 4;
    const int qf = gtid & 7;
    const int sf = gtid >> 3;

    const int worker = blockIdx.x * 2 + group;

    // X staging offsets (each thread handles elements gtid and gtid+256)
    const int xoff0 = (gtid >> 4) * XP + (gtid & 15);
    const int xoff1 = xoff0 + 16 * XP;

    // ---- prologue: stage X for first tile into buffer 0 ----
    {
        const int b0i = worker * (TBS * 16);
        Xq[xoff0] = X[b0i + gtid];
        Xq[xoff1] = X[b0i + gtid + 256];
    }
    asm volatile("bar.sync %0, 256;" :: "r"(gbar) : "memory");
    int xb = 0;

    for (int tile = worker; tile < NTILES; tile += NWORKERS) {
        const int base = tile * TBS;
        float* Xs = Xq + xb * (TBS * XP);

        // ---- prefetch next tile's X into registers ----
        const int nt = tile + NWORKERS;
        float xp0 = 0.f, xp1 = 0.f;
        if (nt < NTILES) {
            xp0 = X[nt*512 + gtid];
            xp1 = X[nt*512 + gtid + 256];
        }

        // ---- phase 1: h1, h1', h1'' (reads Xs[xb]) ----
        {
            float hh[4][4], ee[4][4], ff[4][4];   // [c][ss]
            #pragma unroll
            for (int ss = 0; ss < 4; ss++) {
                const int s = s0 + ss;
                float xr[8], vr[8];
                #pragma unroll
                for (int k = 0; k < 8; k++) { xr[k] = Xs[s*XP + k]; vr[k] = Xs[s*XP + 8 + k]; }
                #pragma unroll
                for (int c = 0; c < 4; c++) {
                    const int i = j0 + c;
                    float z = b0s[i], t = 0.f;
                    #pragma unroll
                    for (int k = 0; k < 8; k++) {
                        float w = W0d[((i<<3) + k) << 1];
                        z = fmaf(w, xr[k], z);
                        t = fmaf(w, vr[k], t);
                    }
                    float h = ftanh(z);
                    float d = 1.f - h*h;
                    float e = d * t;
                    float f = -2.f * h * t * e;
                    hh[c][ss] = h; ee[c][ss] = e; ff[c][ss] = f;
                }
            }
            #pragma unroll
            for (int c = 0; c < 4; c++) {
                const int i = j0 + c;
                *(float4*)(h1s + i*TBS + s0) = make_float4(hh[c][0],hh[c][1],hh[c][2],hh[c][3]);
                *(float4*)(e1s + i*TBS + s0) = make_float4(ee[c][0],ee[c][1],ee[c][2],ee[c][3]);
                *(float4*)(f1s + i*TBS + s0) = make_float4(ff[c][0],ff[c][1],ff[c][2],ff[c][3]);
            }
        }
        asm volatile("bar.sync %0, 256;" :: "r"(gbar) : "memory");   // h/e/f ready

        // ---- store prefetched X into the other buffer (prev phase-5 done) ----
        if (nt < NTILES) {
            float* Xn = Xq + (xb ^ 1) * (TBS * XP);
            Xn[xoff0] = xp0;
            Xn[xoff1] = xp1;
        }

        // ---- phase 2: z2 = W1 h1, P = W1 h1' (f32x2, sample-packed) ----
        ull az2[4][2], ap2[4][2];
        #pragma unroll
        for (int c = 0; c < 4; c++) {
            az2[c][0]=0ull; az2[c][1]=0ull;
            ap2[c][0]=0ull; ap2[c][1]=0ull;
        }
        {
            const float* hp = h1s + s0;
            const float* ep = e1s + s0;
            #pragma unroll 1
            for (int i = 0; i < HID; i += 4) {
                const float4 wr0 = *(const float4*)(W1s + (j0+0)*W1P + i);
                const float4 wr1 = *(const float4*)(W1s + (j0+1)*W1P + i);
                const float4 wr2 = *(const float4*)(W1s + (j0+2)*W1P + i);
                const float4 wr3 = *(const float4*)(W1s + (j0+3)*W1P + i);
                const float* wa0 = (const float*)&wr0;
                const float* wa1 = (const float*)&wr1;
                const float* wa2 = (const float*)&wr2;
                const float* wa3 = (const float*)&wr3;
                #pragma unroll
                for (int ii = 0; ii < 4; ii++) {
                    const ulonglong2 hv = *(const ulonglong2*)(hp + (i+ii)*TBS);
                    const ulonglong2 ev = *(const ulonglong2*)(ep + (i+ii)*TBS);
                    ull w;
                    w = pack2(wa0[ii], wa0[ii]);
                    az2[0][0]=fma2(w,hv.x,az2[0][0]); az2[0][1]=fma2(w,hv.y,az2[0][1]);
                    ap2[0][0]=fma2(w,ev.x,ap2[0][0]); ap2[0][1]=fma2(w,ev.y,ap2[0][1]);
                    w = pack2(wa1[ii], wa1[ii]);
                    az2[1][0]=fma2(w,hv.x,az2[1][0]); az2[1][1]=fma2(w,hv.y,az2[1][1]);
                    ap2[1][0]=fma2(w,ev.x,ap2[1][0]); ap2[1][1]=fma2(w,ev.y,ap2[1][1]);
                    w = pack2(wa2[ii], wa2[ii]);
                    az2[2][0]=fma2(w,hv.x,az2[2][0]); az2[2][1]=fma2(w,hv.y,az2[2][1]);
                    ap2[2][0]=fma2(w,ev.x,ap2[2][0]); ap2[2][1]=fma2(w,ev.y,ap2[2][1]);
                    w = pack2(wa3[ii], wa3[ii]);
                    az2[3][0]=fma2(w,hv.x,az2[3][0]); az2[3][1]=fma2(w,hv.y,az2[3][1]);
                    ap2[3][0]=fma2(w,ev.x,ap2[3][0]); ap2[3][1]=fma2(w,ev.y,ap2[3][1]);
                }
            }
        }

        // ---- phase-2 epilogue (no barrier: writes a_s own rows only) ----
        float hvp[4] = {0.f, 0.f, 0.f, 0.f};
        #pragma unroll
        for (int c = 0; c < 4; c++) {
            const int j = j0 + c;
            const float2 z01 = unpack2(az2[c][0]), z23 = unpack2(az2[c][1]);
            const float2 p01 = unpack2(ap2[c][0]), p23 = unpack2(ap2[c][1]);
            const float zz[4] = {z01.x, z01.y, z23.x, z23.y};
            const float pp[4] = {p01.x, p01.y, p23.x, p23.y};
            const float w2j = w2s[j];
            const float bj  = b1s[j];
            float av[4];
            #pragma unroll
            for (int ss = 0; ss < 4; ss++) {
                float h2 = ftanh(zz[ss] + bj);
                float d2 = 1.f - h2*h2;
                float P = pp[ss];
                hvp[ss] = fmaf(-2.f*w2j, h2*d2*P*P, hvp[ss]);
                av[ss] = d2 * w2j;
            }
            *(float4*)(a_s + j*TBS + s0) = make_float4(av[0],av[1],av[2],av[3]);
        }
        asm volatile("bar.sync %0, 256;" :: "r"(gbar) : "memory");   // a ready

        // ---- phase 3: U = W1^T a (f32x2) ----
        ull au2[4][2];
        #pragma unroll
        for (int c = 0; c < 4; c++) { au2[c][0]=0ull; au2[c][1]=0ull; }
        {
            const float* apnt = a_s + s0;
            #pragma unroll 2
            for (int j = 0; j < HID; j++) {
                const ulonglong2 av = *(const ulonglong2*)(apnt + j*TBS);
                const float4 wv = *(const float4*)(W1s + j*W1P + j0);
                const float* wa = (const float*)&wv;
                ull w;
                w = pack2(wa[0], wa[0]);
                au2[0][0]=fma2(w,av.x,au2[0][0]); au2[0][1]=fma2(w,av.y,au2[0][1]);
                w = pack2(wa[1], wa[1]);
                au2[1][0]=fma2(w,av.x,au2[1][0]); au2[1][1]=fma2(w,av.y,au2[1][1]);
                w = pack2(wa[2], wa[2]);
                au2[2][0]=fma2(w,av.x,au2[2][0]); au2[2][1]=fma2(w,av.y,au2[2][1]);
                w = pack2(wa[3], wa[3]);
                au2[3][0]=fma2(w,av.x,au2[3][0]); au2[3][1]=fma2(w,av.y,au2[3][1]);
            }
        }

        // ---- phase-3 epilogue (own block only): hvv += U.h1''; sbuf = d1*U ----
        #pragma unroll
        for (int c = 0; c < 4; c++) {
            const int i = j0 + c;
            const float2 u01 = unpack2(au2[c][0]), u23 = unpack2(au2[c][1]);
            const float uu[4] = {u01.x, u01.y, u23.x, u23.y};
            const float4 fv = *(const float4*)(f1s + i*TBS + s0);
            const float4 hv = *(const float4*)(h1s + i*TBS + s0);
            const float fpp[4] = {fv.x, fv.y, fv.z, fv.w};
            const float hh4[4] = {hv.x, hv.y, hv.z, hv.w};
            float sv[4];
            #pragma unroll
            for (int ss = 0; ss < 4; ss++) {
                hvp[ss] = fmaf(uu[ss], fpp[ss], hvp[ss]);
                sv[ss]  = (1.f - hh4[ss]*hh4[ss]) * uu[ss];
            }
            *(float4*)(f1s + i*TBS + s0) = make_float4(sv[0],sv[1],sv[2],sv[3]);
        }
        #pragma unroll
        for (int ss = 0; ss < 4; ss++)
            hvp_s[jy*HVP + s0 + ss] = hvp[ss];
        asm volatile("bar.sync %0, 256;" :: "r"(gbar) : "memory");   // sbuf + hvp ready

        // ---- phase 4 (warps 0-3): g = W0^T sbuf || hvv reduce (warp 4) ----
        if (gtid < 128) {
            const int q  = gtid & 7;
            const int sp = gtid >> 3;
            ull acc = 0ull;
            const ull* w0dp = (const ull*)(W0d) + q;
            const float* fp = f1s + 2*sp;
            #pragma unroll 4
            for (int i = 0; i < HID; i++)
                acc = fma2(w0dp[i*8], *(const ull*)(fp + i*TBS), acc);
            float2 gv = unpack2(acc);
            gbf[(2*sp)*GBP + q]   = gv.x;
            gbf[(2*sp+1)*GBP + q] = gv.y;
        } else if (gtid < 160) {
            const int s = gtid - 128;
            float acc = 0.f;
            #pragma unroll
            for (int g = 0; g < 32; g++) acc += hvp_s[g*HVP + s];
            hvs[s] = acc;
        }
        asm volatile("bar.sync %0, 256;" :: "r"(gbar) : "memory");   // gbf + hvs ready

        // ---- phase 5: Sherman-Morrison combine + coalesced store ----
        {
            float g[8];
            #pragma unroll
            for (int k = 0; k < 8; k++) g[k] = gbf[sf*GBP + k];
            float gg = 0.f;
            #pragma unroll
            for (int k = 0; k < 8; k++) gg = fmaf(g[k], g[k], gg);
            float xr[8], vr[8];
            #pragma unroll
            for (int k = 0; k < 8; k++) { xr[k] = Xs[sf*XP + k]; vr[k] = Xs[sf*XP + 8 + k]; }
            float gf = 0.f, fq = 0.f;
            #pragma unroll
            for (int q2 = 0; q2 < 8; q2++) {
                float fo = 0.f;
                #pragma unroll
                for (int k = 0; k < 8; k++) {
                    fo = fmaf(-Ds[q2*8+k], vr[k], fo);
                    fo = fmaf(-Ks[q2*8+k], xr[k], fo);
                }
                gf = fmaf(g[q2], fo, gf);
                if (q2 == qf) fq = fo;
            }
            float scale = (gf + hvs[sf]) / (1.f + gg);
            out[(base + sf)*8 + qf] = fq - g[qf]*scale;
        }
        // no trailing barrier: next-tile hazards all covered by interior barriers
        xb ^= 1;
    }
}

extern "C" void kernel_launch(void* const* d_in, const int* in_sizes, int n_in,
                              void* d_out, int out_size)
{
    const float* X  = (const float*)d_in[0];
    const float* Km = (const float*)d_in[1];
    const float* Dm = (const float*)d_in[2];
    const float* W0 = (const float*)d_in[3];
    const float* b0 = (const float*)d_in[4];
    const float* W1 = (const float*)d_in[5];
    const float* b1 = (const float*)d_in[6];
    const float* W2 = (const float*)d_in[7];

    cudaFuncSetAttribute(dyn_kernel, cudaFuncAttributeMaxDynamicSharedMemorySize,
                         (int)SMEM_BYTES);
    dyn_kernel<<<GRID, NTHREADS, SMEM_BYTES>>>(X, Km, Dm, W0, b0, W1, b1, W2,
                                               (float*)d_out);
}

// round 9
// speedup vs baseline: 3.3330x; 1.0036x over previous
#include <cuda_runtime.h>
#include <math.h>

// Dynamics_79843442033036 — fused analytic grad/HVV kernel.
// Round 9 = round-5 base (best measured) with r=8 register blocking in
// phases 2/3 (halves crossbar wavefronts per output), separate a_s buffer.

typedef unsigned long long ull;

#define HID     128
#define DIMV    8
#define BATCHN  65536
#define TBS     32
#define NTILES  (BATCHN / TBS)      // 2048
#define NTHREADS 512
#define GTHREADS 256
#define GRID    152
#define NWORKERS (GRID * 2)

#define W1P 132
#define XP  17
#define W0P 10
#define HVP 33
#define GBP 9
#define NHG 16                       // hvv partial groups

// ---- shared weights (float offsets) ----
#define SM_W1   0                            // [128][132]
#define SM_W0   (SM_W1 + HID*W1P)            // 16896
#define SM_W0D  (SM_W0 + HID*W0P)            // 18176
#define SM_B0   (SM_W0D + HID*DIMV*2)        // 20224
#define SM_B1   (SM_B0 + HID)
#define SM_W2   (SM_B1 + HID)
#define SM_K    (SM_W2 + HID)
#define SM_D    (SM_K + 64)
#define SM_GRPBASE (SM_D + 64)               // 20736
// ---- per-group region ----
#define G_H1    0                            // [128][32]
#define G_E1    (G_H1 + HID*TBS)             // 4096
#define G_F1    (G_E1 + HID*TBS)             // 8192   h1'' then sbuf
#define G_AS    (G_F1 + HID*TBS)             // 12288  [128][32]
#define G_X     (G_AS + HID*TBS)             // 16384  [32][17]
#define G_G     (G_X + TBS*XP)               // 16928  [32][9]
#define G_HVV   (G_G + TBS*GBP)              // 17216
#define G_HVP   (G_HVV + TBS)                // 17248  [16][33]
#define G_SIZE  (G_HVP + NHG*HVP)            // 17776
#define SM_TOTAL (SM_GRPBASE + 2*G_SIZE)     // 56288 floats = 219.9 KB
#define SMEM_BYTES (SM_TOTAL * sizeof(float))

__device__ __forceinline__ ull pack2(float x, float y) {
    ull r; asm("mov.b64 %0, {%1,%2};" : "=l"(r) : "f"(x), "f"(y)); return r;
}
__device__ __forceinline__ float2 unpack2(ull v) {
    float2 r; asm("mov.b64 {%0,%1}, %2;" : "=f"(r.x), "=f"(r.y) : "l"(v)); return r;
}
__device__ __forceinline__ ull fma2(ull a, ull b, ull c) {
    ull r; asm("fma.rn.f32x2 %0, %1, %2, %3;" : "=l"(r) : "l"(a), "l"(b), "l"(c)); return r;
}
// fast tanh: 1 - 2/(e^{2z}+1). Correct saturation, rel err ~1e-6.
__device__ __forceinline__ float ftanh(float z) {
    float e = __expf(2.f * z);
    return 1.f - __fdividef(2.f, e + 1.f);
}

extern "C" __global__ void __launch_bounds__(NTHREADS, 1)
dyn_kernel(const float* __restrict__ X,  const float* __restrict__ Km,
           const float* __restrict__ Dm, const float* __restrict__ W0,
           const float* __restrict__ b0, const float* __restrict__ W1,
           const float* __restrict__ b1, const float* __restrict__ W2,
           float* __restrict__ out)
{
    extern __shared__ float sm[];
    float* W1s = sm + SM_W1;
    float* W0s = sm + SM_W0;
    float* W0d = sm + SM_W0D;
    float* b0s = sm + SM_B0;
    float* b1s = sm + SM_B1;
    float* w2s = sm + SM_W2;
    float* Ks  = sm + SM_K;
    float* Ds  = sm + SM_D;

    const int tid   = threadIdx.x;
    const int group = tid >> 8;
    const int gtid  = tid & 255;
    const int gbar  = group + 1;

    float* gbase = sm + SM_GRPBASE + group * G_SIZE;
    float* h1s = gbase + G_H1;
    float* e1s = gbase + G_E1;
    float* f1s = gbase + G_F1;
    float* a_s = gbase + G_AS;
    float* Xs  = gbase + G_X;
    float* gbf = gbase + G_G;
    float* hvs = gbase + G_HVV;
    float* hvp_s = gbase + G_HVP;

    // ---- one-time weight staging (whole CTA) ----
    for (int idx = tid; idx < HID*HID; idx += NTHREADS) {
        int j = idx >> 7, i = idx & 127;
        W1s[j*W1P + i] = W1[idx];
    }
    for (int idx = tid; idx < HID*DIMV; idx += NTHREADS) {
        int i = idx >> 3, k = idx & 7;
        float w = W0[idx];
        W0s[i*W0P + k] = w;
        W0d[idx*2]     = w;
        W0d[idx*2 + 1] = w;
    }
    if (tid < HID) { b0s[tid] = b0[tid]; b1s[tid] = b1[tid]; w2s[tid] = W2[tid]; }
    if (tid < 64)  { Ks[tid] = Km[tid]; Ds[tid] = Dm[tid]; }
    __syncthreads();

    // phase-1 mapping (256 threads): 4 rows x 4 samples
    const int tx = gtid & 7;
    const int jy = gtid >> 3;
    const int s0 = tx * 4;
    const int j0 = jy * 4;
    // phase-2/3 mapping (128 threads): 8 rows/cols x 4 samples
    const int gz = gtid >> 3;           // 0..15 for gtid<128
    const int jb = gz * 8;
    // phase-4/5 mapping
    const int qf = gtid & 7;
    const int sf = gtid >> 3;

    const int worker = blockIdx.x * 2 + group;

    for (int tile = worker; tile < NTILES; tile += NWORKERS) {
        const int base = tile * TBS;

        // ---- stage X tile ----
        for (int idx = gtid; idx < TBS*16; idx += GTHREADS) {
            int s = idx >> 4, k = idx & 15;
            Xs[s*XP + k] = X[base*16 + idx];
        }
        asm volatile("bar.sync %0, 256;" :: "r"(gbar) : "memory");   // B1

        // ---- phase 1 (256 threads): h1, h1', h1'' ----
        {
            float hh[4][4], ee[4][4], ff[4][4];   // [c][ss]
            #pragma unroll
            for (int ss = 0; ss < 4; ss++) {
                const int s = s0 + ss;
                float xr[8], vr[8];
                #pragma unroll
                for (int k = 0; k < 8; k++) { xr[k] = Xs[s*XP + k]; vr[k] = Xs[s*XP + 8 + k]; }
                #pragma unroll
                for (int c = 0; c < 4; c++) {
                    const int i = j0 + c;
                    float z = b0s[i], t = 0.f;
                    #pragma unroll
                    for (int k = 0; k < 8; k++) {
                        float w = W0s[i*W0P + k];
                        z = fmaf(w, xr[k], z);
                        t = fmaf(w, vr[k], t);
                    }
                    float h = ftanh(z);
                    float d = 1.f - h*h;
                    float e = d * t;
                    float f = -2.f * h * t * e;
                    hh[c][ss] = h; ee[c][ss] = e; ff[c][ss] = f;
                }
            }
            #pragma unroll
            for (int c = 0; c < 4; c++) {
                const int i = j0 + c;
                *(float4*)(h1s + i*TBS + s0) = make_float4(hh[c][0],hh[c][1],hh[c][2],hh[c][3]);
                *(float4*)(e1s + i*TBS + s0) = make_float4(ee[c][0],ee[c][1],ee[c][2],ee[c][3]);
                *(float4*)(f1s + i*TBS + s0) = make_float4(ff[c][0],ff[c][1],ff[c][2],ff[c][3]);
            }
        }
        asm volatile("bar.sync %0, 256;" :: "r"(gbar) : "memory");   // B2 h/e/f ready

        float hvp[4] = {0.f, 0.f, 0.f, 0.f};

        // ---- phase 2 (128 threads): z2 = W1 h1, P = W1 h1', r=8 blocking ----
        if (gtid < 128) {
            ull az[8][2], ap[8][2];
            #pragma unroll
            for (int r = 0; r < 8; r++) {
                az[r][0]=0ull; az[r][1]=0ull;
                ap[r][0]=0ull; ap[r][1]=0ull;
            }
            const float* hp = h1s + s0;
            const float* ep = e1s + s0;
            #pragma unroll 1
            for (int i = 0; i < HID; i += 4) {
                float4 wr[8];
                #pragma unroll
                for (int r = 0; r < 8; r++)
                    wr[r] = *(const float4*)(W1s + (jb+r)*W1P + i);
                #pragma unroll
                for (int ii = 0; ii < 4; ii++) {
                    const ulonglong2 hv = *(const ulonglong2*)(hp + (i+ii)*TBS);
                    const ulonglong2 ev = *(const ulonglong2*)(ep + (i+ii)*TBS);
                    #pragma unroll
                    for (int r = 0; r < 8; r++) {
                        const float w = ((const float*)&wr[r])[ii];
                        const ull wp = pack2(w, w);
                        az[r][0]=fma2(wp,hv.x,az[r][0]); az[r][1]=fma2(wp,hv.y,az[r][1]);
                        ap[r][0]=fma2(wp,ev.x,ap[r][0]); ap[r][1]=fma2(wp,ev.y,ap[r][1]);
                    }
                }
            }
            // ---- phase-2 epilogue: a = d2*w2 -> a_s ; P-term hvv in regs ----
            #pragma unroll
            for (int r = 0; r < 8; r++) {
                const int j = jb + r;
                const float2 z01 = unpack2(az[r][0]), z23 = unpack2(az[r][1]);
                const float2 p01 = unpack2(ap[r][0]), p23 = unpack2(ap[r][1]);
                const float zz[4] = {z01.x, z01.y, z23.x, z23.y};
                const float pp[4] = {p01.x, p01.y, p23.x, p23.y};
                const float w2j = w2s[j];
                const float bj  = b1s[j];
                float av[4];
                #pragma unroll
                for (int ss = 0; ss < 4; ss++) {
                    float h2 = ftanh(zz[ss] + bj);
                    float d2 = 1.f - h2*h2;
                    float P = pp[ss];
                    hvp[ss] = fmaf(-2.f*w2j, h2*d2*P*P, hvp[ss]);
                    av[ss] = d2 * w2j;
                }
                *(float4*)(a_s + j*TBS + s0) = make_float4(av[0],av[1],av[2],av[3]);
            }
        }
        asm volatile("bar.sync %0, 256;" :: "r"(gbar) : "memory");   // B3 a ready

        // ---- phase 3 (128 threads): U = W1^T a, 8 cols x 4 samples ----
        if (gtid < 128) {
            ull au[8][2];
            #pragma unroll
            for (int c = 0; c < 8; c++) { au[c][0]=0ull; au[c][1]=0ull; }
            const float* apnt = a_s + s0;
            #pragma unroll 2
            for (int j = 0; j < HID; j++) {
                const ulonglong2 av = *(const ulonglong2*)(apnt + j*TBS);
                const float4 wv0 = *(const float4*)(W1s + j*W1P + jb);
                const float4 wv1 = *(const float4*)(W1s + j*W1P + jb + 4);
                const float* wa0 = (const float*)&wv0;
                const float* wa1 = (const float*)&wv1;
                #pragma unroll
                for (int c = 0; c < 4; c++) {
                    const ull wp = pack2(wa0[c], wa0[c]);
                    au[c][0]=fma2(wp,av.x,au[c][0]); au[c][1]=fma2(wp,av.y,au[c][1]);
                }
                #pragma unroll
                for (int c = 0; c < 4; c++) {
                    const ull wp = pack2(wa1[c], wa1[c]);
                    au[4+c][0]=fma2(wp,av.x,au[4+c][0]); au[4+c][1]=fma2(wp,av.y,au[4+c][1]);
                }
            }
            // ---- phase-3 epilogue: hvv += U.h1''; sbuf(f1s) = d1*U ----
            #pragma unroll
            for (int c = 0; c < 8; c++) {
                const int i = jb + c;
                const float2 u01 = unpack2(au[c][0]), u23 = unpack2(au[c][1]);
                const float uu[4] = {u01.x, u01.y, u23.x, u23.y};
                const float4 fv = *(const float4*)(f1s + i*TBS + s0);
                const float4 hv = *(const float4*)(h1s + i*TBS + s0);
                const float fpp[4] = {fv.x, fv.y, fv.z, fv.w};
                const float hh4[4] = {hv.x, hv.y, hv.z, hv.w};
                float sv[4];
                #pragma unroll
                for (int ss = 0; ss < 4; ss++) {
                    hvp[ss] = fmaf(uu[ss], fpp[ss], hvp[ss]);
                    sv[ss]  = (1.f - hh4[ss]*hh4[ss]) * uu[ss];
                }
                *(float4*)(f1s + i*TBS + s0) = make_float4(sv[0],sv[1],sv[2],sv[3]);
            }
            #pragma unroll
            for (int ss = 0; ss < 4; ss++)
                hvp_s[gz*HVP + s0 + ss] = hvp[ss];
        }
        asm volatile("bar.sync %0, 256;" :: "r"(gbar) : "memory");   // B4 sbuf+hvp ready

        // ---- phase 4 (warps 0-3): g = W0^T sbuf || hvv reduce (warp 4) ----
        if (gtid < 128) {
            const int q  = gtid & 7;
            const int sp = gtid >> 3;
            ull acc = 0ull;
            const ull* w0dp = (const ull*)(W0d) + q;
            const float* fp = f1s + 2*sp;
            #pragma unroll 4
            for (int i = 0; i < HID; i++)
                acc = fma2(w0dp[i*8], *(const ull*)(fp + i*TBS), acc);
            float2 gv = unpack2(acc);
            gbf[(2*sp)*GBP + q]   = gv.x;
            gbf[(2*sp+1)*GBP + q] = gv.y;
        } else if (gtid < 160) {
            const int s = gtid - 128;
            float acc = 0.f;
            #pragma unroll
            for (int g = 0; g < NHG; g++) acc += hvp_s[g*HVP + s];
            hvs[s] = acc;
        }
        asm volatile("bar.sync %0, 256;" :: "r"(gbar) : "memory");   // B5 gbf+hvs ready

        // ---- phase 5: Sherman-Morrison combine + coalesced store ----
        {
            float g[8];
            #pragma unroll
            for (int k = 0; k < 8; k++) g[k] = gbf[sf*GBP + k];
            float gg = 0.f;
            #pragma unroll
            for (int k = 0; k < 8; k++) gg = fmaf(g[k], g[k], gg);
            float xr[8], vr[8];
            #pragma unroll
            for (int k = 0; k < 8; k++) { xr[k] = Xs[sf*XP + k]; vr[k] = Xs[sf*XP + 8 + k]; }
            float gf = 0.f, fq = 0.f;
            #pragma unroll
            for (int q2 = 0; q2 < 8; q2++) {
                float fo = 0.f;
                #pragma unroll
                for (int k = 0; k < 8; k++) {
                    fo = fmaf(-Ds[q2*8+k], vr[k], fo);
                    fo = fmaf(-Ks[q2*8+k], xr[k], fo);
                }
                gf = fmaf(g[q2], fo, gf);
                if (q2 == qf) fq = fo;
            }
            float scale = (gf + hvs[sf]) / (1.f + gg);
            out[(base + sf)*8 + qf] = fq - g[qf]*scale;
        }
        asm volatile("bar.sync %0, 256;" :: "r"(gbar) : "memory");   // B6 Xs safe
    }
}

extern "C" void kernel_launch(void* const* d_in, const int* in_sizes, int n_in,
                              void* d_out, int out_size)
{
    const float* X  = (const float*)d_in[0];
    const float* Km = (const float*)d_in[1];
    const float* Dm = (const float*)d_in[2];
    const float* W0 = (const float*)d_in[3];
    const float* b0 = (const float*)d_in[4];
    const float* W1 = (const float*)d_in[5];
    const float* b1 = (const float*)d_in[6];
    const float* W2 = (const float*)d_in[7];

    cudaFuncSetAttribute(dyn_kernel, cudaFuncAttributeMaxDynamicSharedMemorySize,
                         (int)SMEM_BYTES);
    dyn_kernel<<<GRID, NTHREADS, SMEM_BYTES>>>(X, Km, Dm, W0, b0, W1, b1, W2,
                                               (float*)d_out);
}

// round 10
// speedup vs baseline: 3.3592x; 1.0079x over previous
#include <cuda_runtime.h>
#include <math.h>

// Dynamics_79843442033036 — fused analytic grad/HVV kernel.
// Round 9 = round-5 base (best measured) with r=8 register blocking in
// phases 2/3 (halves crossbar wavefronts per output), separate a_s buffer.

typedef unsigned long long ull;

#define HID     128
#define DIMV    8
#define BATCHN  65536
#define TBS     32
#define NTILES  (BATCHN / TBS)      // 2048
#define NTHREADS 512
#define GTHREADS 256
#define GRID    152
#define NWORKERS (GRID * 2)

#define W1P 132
#define XP  17
#define W0P 10
#define HVP 33
#define GBP 9
#define NHG 16                       // hvv partial groups

// ---- shared weights (float offsets) ----
#define SM_W1   0                            // [128][132]
#define SM_W0   (SM_W1 + HID*W1P)            // 16896
#define SM_W0D  (SM_W0 + HID*W0P)            // 18176
#define SM_B0   (SM_W0D + HID*DIMV*2)        // 20224
#define SM_B1   (SM_B0 + HID)
#define SM_W2   (SM_B1 + HID)
#define SM_K    (SM_W2 + HID)
#define SM_D    (SM_K + 64)
#define SM_GRPBASE (SM_D + 64)               // 20736
// ---- per-group region ----
#define G_H1    0                            // [128][32]
#define G_E1    (G_H1 + HID*TBS)             // 4096
#define G_F1    (G_E1 + HID*TBS)             // 8192   h1'' then sbuf
#define G_AS    (G_F1 + HID*TBS)             // 12288  [128][32]
#define G_X     (G_AS + HID*TBS)             // 16384  [32][17]
#define G_G     (G_X + TBS*XP)               // 16928  [32][9]
#define G_HVV   (G_G + TBS*GBP)              // 17216
#define G_HVP   (G_HVV + TBS)                // 17248  [16][33]
#define G_SIZE  (G_HVP + NHG*HVP)            // 17776
#define SM_TOTAL (SM_GRPBASE + 2*G_SIZE)     // 56288 floats = 219.9 KB
#define SMEM_BYTES (SM_TOTAL * sizeof(float))

__device__ __forceinline__ ull pack2(float x, float y) {
    ull r; asm("mov.b64 %0, {%1,%2};" : "=l"(r) : "f"(x), "f"(y)); return r;
}
__device__ __forceinline__ float2 unpack2(ull v) {
    float2 r; asm("mov.b64 {%0,%1}, %2;" : "=f"(r.x), "=f"(r.y) : "l"(v)); return r;
}
__device__ __forceinline__ ull fma2(ull a, ull b, ull c) {
    ull r; asm("fma.rn.f32x2 %0, %1, %2, %3;" : "=l"(r) : "l"(a), "l"(b), "l"(c)); return r;
}
// fast tanh: 1 - 2/(e^{2z}+1). Correct saturation, rel err ~1e-6.
__device__ __forceinline__ float ftanh(float z) {
    float e = __expf(2.f * z);
    return 1.f - __fdividef(2.f, e + 1.f);
}

extern "C" __global__ void __launch_bounds__(NTHREADS, 1)
dyn_kernel(const float* __restrict__ X,  const float* __restrict__ Km,
           const float* __restrict__ Dm, const float* __restrict__ W0,
           const float* __restrict__ b0, const float* __restrict__ W1,
           const float* __restrict__ b1, const float* __restrict__ W2,
           float* __restrict__ out)
{
    extern __shared__ float sm[];
    float* W1s = sm + SM_W1;
    float* W0s = sm + SM_W0;
    float* W0d = sm + SM_W0D;
    float* b0s = sm + SM_B0;
    float* b1s = sm + SM_B1;
    float* w2s = sm + SM_W2;
    float* Ks  = sm + SM_K;
    float* Ds  = sm + SM_D;

    const int tid   = threadIdx.x;
    const int group = tid >> 8;
    const int gtid  = tid & 255;
    const int gbar  = group + 1;

    float* gbase = sm + SM_GRPBASE + group * G_SIZE;
    float* h1s = gbase + G_H1;
    float* e1s = gbase + G_E1;
    float* f1s = gbase + G_F1;
    float* a_s = gbase + G_AS;
    float* Xs  = gbase + G_X;
    float* gbf = gbase + G_G;
    float* hvs = gbase + G_HVV;
    float* hvp_s = gbase + G_HVP;

    // ---- one-time weight staging (whole CTA) ----
    for (int idx = tid; idx < HID*HID; idx += NTHREADS) {
        int j = idx >> 7, i = idx & 127;
        W1s[j*W1P + i] = W1[idx];
    }
    for (int idx = tid; idx < HID*DIMV; idx += NTHREADS) {
        int i = idx >> 3, k = idx & 7;
        float w = W0[idx];
        W0s[i*W0P + k] = w;
        W0d[idx*2]     = w;
        W0d[idx*2 + 1] = w;
    }
    if (tid < HID) { b0s[tid] = b0[tid]; b1s[tid] = b1[tid]; w2s[tid] = W2[tid]; }
    if (tid < 64)  { Ks[tid] = Km[tid]; Ds[tid] = Dm[tid]; }
    __syncthreads();

    // phase-1 mapping (256 threads): 4 rows x 4 samples
    const int tx = gtid & 7;
    const int jy = gtid >> 3;
    const int s0 = tx * 4;
    const int j0 = jy * 4;
    // phase-2/3 mapping (128 threads): 8 rows/cols x 4 samples
    const int gz = gtid >> 3;           // 0..15 for gtid<128
    const int jb = gz * 8;
    // phase-4/5 mapping
    const int qf = gtid & 7;
    const int sf = gtid >> 3;

    const int worker = blockIdx.x * 2 + group;

    for (int tile = worker; tile < NTILES; tile += NWORKERS) {
        const int base = tile * TBS;

        // ---- stage X tile ----
        for (int idx = gtid; idx < TBS*16; idx += GTHREADS) {
            int s = idx >> 4, k = idx & 15;
            Xs[s*XP + k] = X[base*16 + idx];
        }
        asm volatile("bar.sync %0, 256;" :: "r"(gbar) : "memory");   // B1

        // ---- phase 1 (256 threads): h1, h1', h1'' ----
        {
            float hh[4][4], ee[4][4], ff[4][4];   // [c][ss]
            #pragma unroll
            for (int ss = 0; ss < 4; ss++) {
                const int s = s0 + ss;
                float xr[8], vr[8];
                #pragma unroll
                for (int k = 0; k < 8; k++) { xr[k] = Xs[s*XP + k]; vr[k] = Xs[s*XP + 8 + k]; }
                #pragma unroll
                for (int c = 0; c < 4; c++) {
                    const int i = j0 + c;
                    float z = b0s[i], t = 0.f;
                    #pragma unroll
                    for (int k = 0; k < 8; k++) {
                        float w = W0s[i*W0P + k];
                        z = fmaf(w, xr[k], z);
                        t = fmaf(w, vr[k], t);
                    }
                    float h = ftanh(z);
                    float d = 1.f - h*h;
                    float e = d * t;
                    float f = -2.f * h * t * e;
                    hh[c][ss] = h; ee[c][ss] = e; ff[c][ss] = f;
                }
            }
            #pragma unroll
            for (int c = 0; c < 4; c++) {
                const int i = j0 + c;
                *(float4*)(h1s + i*TBS + s0) = make_float4(hh[c][0],hh[c][1],hh[c][2],hh[c][3]);
                *(float4*)(e1s + i*TBS + s0) = make_float4(ee[c][0],ee[c][1],ee[c][2],ee[c][3]);
                *(float4*)(f1s + i*TBS + s0) = make_float4(ff[c][0],ff[c][1],ff[c][2],ff[c][3]);
            }
        }
        asm volatile("bar.sync %0, 256;" :: "r"(gbar) : "memory");   // B2 h/e/f ready

        float hvp[4] = {0.f, 0.f, 0.f, 0.f};

        // ---- phase 2 (128 threads): z2 = W1 h1, P = W1 h1', r=8 blocking ----
        if (gtid < 128) {
            ull az[8][2], ap[8][2];
            #pragma unroll
            for (int r = 0; r < 8; r++) {
                az[r][0]=0ull; az[r][1]=0ull;
                ap[r][0]=0ull; ap[r][1]=0ull;
            }
            const float* hp = h1s + s0;
            const float* ep = e1s + s0;
            #pragma unroll 1
            for (int i = 0; i < HID; i += 4) {
                float4 wr[8];
                #pragma unroll
                for (int r = 0; r < 8; r++)
                    wr[r] = *(const float4*)(W1s + (jb+r)*W1P + i);
                #pragma unroll
                for (int ii = 0; ii < 4; ii++) {
                    const ulonglong2 hv = *(const ulonglong2*)(hp + (i+ii)*TBS);
                    const ulonglong2 ev = *(const ulonglong2*)(ep + (i+ii)*TBS);
                    #pragma unroll
                    for (int r = 0; r < 8; r++) {
                        const float w = ((const float*)&wr[r])[ii];
                        const ull wp = pack2(w, w);
                        az[r][0]=fma2(wp,hv.x,az[r][0]); az[r][1]=fma2(wp,hv.y,az[r][1]);
                        ap[r][0]=fma2(wp,ev.x,ap[r][0]); ap[r][1]=fma2(wp,ev.y,ap[r][1]);
                    }
                }
            }
            // ---- phase-2 epilogue: a = d2*w2 -> a_s ; P-term hvv in regs ----
            #pragma unroll
            for (int r = 0; r < 8; r++) {
                const int j = jb + r;
                const float2 z01 = unpack2(az[r][0]), z23 = unpack2(az[r][1]);
                const float2 p01 = unpack2(ap[r][0]), p23 = unpack2(ap[r][1]);
                const float zz[4] = {z01.x, z01.y, z23.x, z23.y};
                const float pp[4] = {p01.x, p01.y, p23.x, p23.y};
                const float w2j = w2s[j];
                const float bj  = b1s[j];
                float av[4];
                #pragma unroll
                for (int ss = 0; ss < 4; ss++) {
                    float h2 = ftanh(zz[ss] + bj);
                    float d2 = 1.f - h2*h2;
                    float P = pp[ss];
                    hvp[ss] = fmaf(-2.f*w2j, h2*d2*P*P, hvp[ss]);
                    av[ss] = d2 * w2j;
                }
                *(float4*)(a_s + j*TBS + s0) = make_float4(av[0],av[1],av[2],av[3]);
            }
        }
        asm volatile("bar.sync %0, 256;" :: "r"(gbar) : "memory");   // B3 a ready

        // ---- phase 3 (128 threads): U = W1^T a, 8 cols x 4 samples ----
        if (gtid < 128) {
            ull au[8][2];
            #pragma unroll
            for (int c = 0; c < 8; c++) { au[c][0]=0ull; au[c][1]=0ull; }
            const float* apnt = a_s + s0;
            #pragma unroll 2
            for (int j = 0; j < HID; j++) {
                const ulonglong2 av = *(const ulonglong2*)(apnt + j*TBS);
                const float4 wv0 = *(const float4*)(W1s + j*W1P + jb);
                const float4 wv1 = *(const float4*)(W1s + j*W1P + jb + 4);
                const float* wa0 = (const float*)&wv0;
                const float* wa1 = (const float*)&wv1;
                #pragma unroll
                for (int c = 0; c < 4; c++) {
                    const ull wp = pack2(wa0[c], wa0[c]);
                    au[c][0]=fma2(wp,av.x,au[c][0]); au[c][1]=fma2(wp,av.y,au[c][1]);
                }
                #pragma unroll
                for (int c = 0; c < 4; c++) {
                    const ull wp = pack2(wa1[c], wa1[c]);
                    au[4+c][0]=fma2(wp,av.x,au[4+c][0]); au[4+c][1]=fma2(wp,av.y,au[4+c][1]);
                }
            }
            // ---- phase-3 epilogue: hvv += U.h1''; sbuf(f1s) = d1*U ----
            #pragma unroll
            for (int c = 0; c < 8; c++) {
                const int i = jb + c;
                const float2 u01 = unpack2(au[c][0]), u23 = unpack2(au[c][1]);
                const float uu[4] = {u01.x, u01.y, u23.x, u23.y};
                const float4 fv = *(const float4*)(f1s + i*TBS + s0);
                const float4 hv = *(const float4*)(h1s + i*TBS + s0);
                const float fpp[4] = {fv.x, fv.y, fv.z, fv.w};
                const float hh4[4] = {hv.x, hv.y, hv.z, hv.w};
                float sv[4];
                #pragma unroll
                for (int ss = 0; ss < 4; ss++) {
                    hvp[ss] = fmaf(uu[ss], fpp[ss], hvp[ss]);
                    sv[ss]  = (1.f - hh4[ss]*hh4[ss]) * uu[ss];
                }
                *(float4*)(f1s + i*TBS + s0) = make_float4(sv[0],sv[1],sv[2],sv[3]);
            }
            #pragma unroll
            for (int ss = 0; ss < 4; ss++)
                hvp_s[gz*HVP + s0 + ss] = hvp[ss];
        }
        asm volatile("bar.sync %0, 256;" :: "r"(gbar) : "memory");   // B4 sbuf+hvp ready

        // ---- phase 4 (warps 0-3): g = W0^T sbuf || hvv reduce (warp 4) ----
        if (gtid < 128) {
            const int q  = gtid & 7;
            const int sp = gtid >> 3;
            ull acc = 0ull;
            const ull* w0dp = (const ull*)(W0d) + q;
            const float* fp = f1s + 2*sp;
            #pragma unroll 4
            for (int i = 0; i < HID; i++)
                acc = fma2(w0dp[i*8], *(const ull*)(fp + i*TBS), acc);
            float2 gv = unpack2(acc);
            gbf[(2*sp)*GBP + q]   = gv.x;
            gbf[(2*sp+1)*GBP + q] = gv.y;
        } else if (gtid < 160) {
            const int s = gtid - 128;
            float acc = 0.f;
            #pragma unroll
            for (int g = 0; g < NHG; g++) acc += hvp_s[g*HVP + s];
            hvs[s] = acc;
        }
        asm volatile("bar.sync %0, 256;" :: "r"(gbar) : "memory");   // B5 gbf+hvs ready

        // ---- phase 5: Sherman-Morrison combine + coalesced store ----
        {
            float g[8];
            #pragma unroll
            for (int k = 0; k < 8; k++) g[k] = gbf[sf*GBP + k];
            float gg = 0.f;
            #pragma unroll
            for (int k = 0; k < 8; k++) gg = fmaf(g[k], g[k], gg);
            float xr[8], vr[8];
            #pragma unroll
            for (int k = 0; k < 8; k++) { xr[k] = Xs[sf*XP + k]; vr[k] = Xs[sf*XP + 8 + k]; }
            float gf = 0.f, fq = 0.f;
            #pragma unroll
            for (int q2 = 0; q2 < 8; q2++) {
                float fo = 0.f;
                #pragma unroll
                for (int k = 0; k < 8; k++) {
                    fo = fmaf(-Ds[q2*8+k], vr[k], fo);
                    fo = fmaf(-Ks[q2*8+k], xr[k], fo);
                }
                gf = fmaf(g[q2], fo, gf);
                if (q2 == qf) fq = fo;
            }
            float scale = (gf + hvs[sf]) / (1.f + gg);
            out[(base + sf)*8 + qf] = fq - g[qf]*scale;
        }
        asm volatile("bar.sync %0, 256;" :: "r"(gbar) : "memory");   // B6 Xs safe
    }
}

extern "C" void kernel_launch(void* const* d_in, const int* in_sizes, int n_in,
                              void* d_out, int out_size)
{
    const float* X  = (const float*)d_in[0];
    const float* Km = (const float*)d_in[1];
    const float* Dm = (const float*)d_in[2];
    const float* W0 = (const float*)d_in[3];
    const float* b0 = (const float*)d_in[4];
    const float* W1 = (const float*)d_in[5];
    const float* b1 = (const float*)d_in[6];
    const float* W2 = (const float*)d_in[7];

    cudaFuncSetAttribute(dyn_kernel, cudaFuncAttributeMaxDynamicSharedMemorySize,
                         (int)SMEM_BYTES);
    dyn_kernel<<<GRID, NTHREADS, SMEM_BYTES>>>(X, Km, Dm, W0, b0, W1, b1, W2,
                                               (float*)d_out);
}

// round 11
// speedup vs baseline: 3.5651x; 1.0613x over previous
#include <cuda_runtime.h>
#include <math.h>

// Dynamics_79843442033036 — fused analytic grad/HVV kernel.
// Round 11 = round-5 base (best measured, W1P=132, r=4, 256-thread groups)
// + a_s buffer (one less barrier) + double-buffered X prefetch (two less)
// + warp-shuffle hvv reduction (reduce step removed). 4 barriers/tile.

typedef unsigned long long ull;

#define HID     128
#define DIMV    8
#define BATCHN  65536
#define TBS     32
#define NTILES  (BATCHN / TBS)      // 2048
#define NTHREADS 512
#define GTHREADS 256
#define GRID    152
#define NWORKERS (GRID * 2)

#define W1P 132
#define XP  17
#define W0P 10
#define HVP 33                       // hvv per-warp partials pitch
#define GBP 9

// ---- shared weights (float offsets) ----
#define SM_W1   0                            // [128][132]
#define SM_W0   (SM_W1 + HID*W1P)            // 16896
#define SM_W0D  (SM_W0 + HID*W0P)            // 18176
#define SM_B0   (SM_W0D + HID*DIMV*2)        // 20224
#define SM_B1   (SM_B0 + HID)
#define SM_W2   (SM_B1 + HID)
#define SM_K    (SM_W2 + HID)
#define SM_D    (SM_K + 64)
#define SM_GRPBASE (SM_D + 64)               // 20736
// ---- per-group region ----
#define G_H1    0                            // [128][32]
#define G_E1    (G_H1 + HID*TBS)             // 4096
#define G_F1    (G_E1 + HID*TBS)             // 8192   h1'' then sbuf
#define G_AS    (G_F1 + HID*TBS)             // 12288  [128][32]
#define G_X     (G_AS + HID*TBS)             // 16384  2 x [32][17]
#define G_G     (G_X + 2*TBS*XP)             // 17472  [32][9]
#define G_HVP   (G_G + TBS*GBP)              // 17760  [8][33]
#define G_SIZE  (G_HVP + 8*HVP)              // 18024
#define SM_TOTAL (SM_GRPBASE + 2*G_SIZE)     // 56784 floats = 227136 B
#define SMEM_BYTES (SM_TOTAL * sizeof(float))

__device__ __forceinline__ ull pack2(float x, float y) {
    ull r; asm("mov.b64 %0, {%1,%2};" : "=l"(r) : "f"(x), "f"(y)); return r;
}
__device__ __forceinline__ float2 unpack2(ull v) {
    float2 r; asm("mov.b64 {%0,%1}, %2;" : "=f"(r.x), "=f"(r.y) : "l"(v)); return r;
}
__device__ __forceinline__ ull fma2(ull a, ull b, ull c) {
    ull r; asm("fma.rn.f32x2 %0, %1, %2, %3;" : "=l"(r) : "l"(a), "l"(b), "l"(c)); return r;
}
// fast tanh: 1 - 2/(e^{2z}+1). Correct saturation, rel err ~1e-6.
__device__ __forceinline__ float ftanh(float z) {
    float e = __expf(2.f * z);
    return 1.f - __fdividef(2.f, e + 1.f);
}

extern "C" __global__ void __launch_bounds__(NTHREADS, 1)
dyn_kernel(const float* __restrict__ X,  const float* __restrict__ Km,
           const float* __restrict__ Dm, const float* __restrict__ W0,
           const float* __restrict__ b0, const float* __restrict__ W1,
           const float* __restrict__ b1, const float* __restrict__ W2,
           float* __restrict__ out)
{
    extern __shared__ float sm[];
    float* W1s = sm + SM_W1;
    float* W0s = sm + SM_W0;
    float* W0d = sm + SM_W0D;
    float* b0s = sm + SM_B0;
    float* b1s = sm + SM_B1;
    float* w2s = sm + SM_W2;
    float* Ks  = sm + SM_K;
    float* Ds  = sm + SM_D;

    const int tid   = threadIdx.x;
    const int group = tid >> 8;
    const int gtid  = tid & 255;
    const int gbar  = group + 1;

    float* gbase = sm + SM_GRPBASE + group * G_SIZE;
    float* h1s = gbase + G_H1;
    float* e1s = gbase + G_E1;
    float* f1s = gbase + G_F1;
    float* a_s = gbase + G_AS;
    float* Xq  = gbase + G_X;
    float* gbf = gbase + G_G;
    float* hvp_s = gbase + G_HVP;

    // ---- one-time weight staging (whole CTA) ----
    for (int idx = tid; idx < HID*HID; idx += NTHREADS) {
        int j = idx >> 7, i = idx & 127;
        W1s[j*W1P + i] = W1[idx];
    }
    for (int idx = tid; idx < HID*DIMV; idx += NTHREADS) {
        int i = idx >> 3, k = idx & 7;
        float w = W0[idx];
        W0s[i*W0P + k] = w;
        W0d[idx*2]     = w;
        W0d[idx*2 + 1] = w;
    }
    if (tid < HID) { b0s[tid] = b0[tid]; b1s[tid] = b1[tid]; w2s[tid] = W2[tid]; }
    if (tid < 64)  { Ks[tid] = Km[tid]; Ds[tid] = Dm[tid]; }
    __syncthreads();

    const int tx = gtid & 7;            // 8 sample-groups x 4 samples
    const int jy = gtid >> 3;           // 32 hidden-groups x 4 rows
    const int s0 = tx * 4;
    const int j0 = jy * 4;
    const int qf = gtid & 7;
    const int sf = gtid >> 3;
    const int wrp = gtid >> 5;          // warp id in group (0..7)

    const int worker = blockIdx.x * 2 + group;

    // X staging offsets (each thread stages 2 elements)
    const int xoff0 = (gtid >> 4) * XP + (gtid & 15);
    const int xoff1 = xoff0 + 16 * XP;

    // ---- prologue: stage X for first tile into buffer 0 ----
    {
        const int b0i = worker * (TBS * 16);
        Xq[xoff0] = X[b0i + gtid];
        Xq[xoff1] = X[b0i + gtid + 256];
    }
    asm volatile("bar.sync %0, 256;" :: "r"(gbar) : "memory");
    int xb = 0;

    for (int tile = worker; tile < NTILES; tile += NWORKERS) {
        const int base = tile * TBS;
        float* Xs = Xq + xb * (TBS * XP);

        // ---- prefetch next tile's X into registers ----
        const int nt = tile + NWORKERS;
        float xp0 = 0.f, xp1 = 0.f;
        if (nt < NTILES) {
            xp0 = X[nt*512 + gtid];
            xp1 = X[nt*512 + gtid + 256];
        }

        // ---- phase 1: h1, h1', h1'' ----
        {
            float hh[4][4], ee[4][4], ff[4][4];   // [c][ss]
            #pragma unroll
            for (int ss = 0; ss < 4; ss++) {
                const int s = s0 + ss;
                float xr[8], vr[8];
                #pragma unroll
                for (int k = 0; k < 8; k++) { xr[k] = Xs[s*XP + k]; vr[k] = Xs[s*XP + 8 + k]; }
                #pragma unroll
                for (int c = 0; c < 4; c++) {
                    const int i = j0 + c;
                    float z = b0s[i], t = 0.f;
                    #pragma unroll
                    for (int k = 0; k < 8; k++) {
                        float w = W0s[i*W0P + k];
                        z = fmaf(w, xr[k], z);
                        t = fmaf(w, vr[k], t);
                    }
                    float h = ftanh(z);
                    float d = 1.f - h*h;
                    float e = d * t;
                    float f = -2.f * h * t * e;
                    hh[c][ss] = h; ee[c][ss] = e; ff[c][ss] = f;
                }
            }
            #pragma unroll
            for (int c = 0; c < 4; c++) {
                const int i = j0 + c;
                *(float4*)(h1s + i*TBS + s0) = make_float4(hh[c][0],hh[c][1],hh[c][2],hh[c][3]);
                *(float4*)(e1s + i*TBS + s0) = make_float4(ee[c][0],ee[c][1],ee[c][2],ee[c][3]);
                *(float4*)(f1s + i*TBS + s0) = make_float4(ff[c][0],ff[c][1],ff[c][2],ff[c][3]);
            }
        }
        asm volatile("bar.sync %0, 256;" :: "r"(gbar) : "memory");   // B2: h/e/f ready

        // ---- store prefetched X into the other buffer (prev reads done @ B2) ----
        if (nt < NTILES) {
            float* Xn = Xq + (xb ^ 1) * (TBS * XP);
            Xn[xoff0] = xp0;
            Xn[xoff1] = xp1;
        }

        // ---- phase 2: z2 = W1 h1, P = W1 h1' (f32x2, sample-packed) ----
        ull az2[4][2], ap2[4][2];
        #pragma unroll
        for (int c = 0; c < 4; c++) {
            az2[c][0]=0ull; az2[c][1]=0ull;
            ap2[c][0]=0ull; ap2[c][1]=0ull;
        }
        {
            const float* hp = h1s + s0;
            const float* ep = e1s + s0;
            #pragma unroll 1
            for (int i = 0; i < HID; i += 4) {
                const float4 wr0 = *(const float4*)(W1s + (j0+0)*W1P + i);
                const float4 wr1 = *(const float4*)(W1s + (j0+1)*W1P + i);
                const float4 wr2 = *(const float4*)(W1s + (j0+2)*W1P + i);
                const float4 wr3 = *(const float4*)(W1s + (j0+3)*W1P + i);
                const float* wa0 = (const float*)&wr0;
                const float* wa1 = (const float*)&wr1;
                const float* wa2 = (const float*)&wr2;
                const float* wa3 = (const float*)&wr3;
                #pragma unroll
                for (int ii = 0; ii < 4; ii++) {
                    const ulonglong2 hv = *(const ulonglong2*)(hp + (i+ii)*TBS);
                    const ulonglong2 ev = *(const ulonglong2*)(ep + (i+ii)*TBS);
                    ull w;
                    w = pack2(wa0[ii], wa0[ii]);
                    az2[0][0]=fma2(w,hv.x,az2[0][0]); az2[0][1]=fma2(w,hv.y,az2[0][1]);
                    ap2[0][0]=fma2(w,ev.x,ap2[0][0]); ap2[0][1]=fma2(w,ev.y,ap2[0][1]);
                    w = pack2(wa1[ii], wa1[ii]);
                    az2[1][0]=fma2(w,hv.x,az2[1][0]); az2[1][1]=fma2(w,hv.y,az2[1][1]);
                    ap2[1][0]=fma2(w,ev.x,ap2[1][0]); ap2[1][1]=fma2(w,ev.y,ap2[1][1]);
                    w = pack2(wa2[ii], wa2[ii]);
                    az2[2][0]=fma2(w,hv.x,az2[2][0]); az2[2][1]=fma2(w,hv.y,az2[2][1]);
                    ap2[2][0]=fma2(w,ev.x,ap2[2][0]); ap2[2][1]=fma2(w,ev.y,ap2[2][1]);
                    w = pack2(wa3[ii], wa3[ii]);
                    az2[3][0]=fma2(w,hv.x,az2[3][0]); az2[3][1]=fma2(w,hv.y,az2[3][1]);
                    ap2[3][0]=fma2(w,ev.x,ap2[3][0]); ap2[3][1]=fma2(w,ev.y,ap2[3][1]);
                }
            }
        }

        // ---- phase-2 epilogue (no barrier: a_s own rows only) ----
        float hvp[4] = {0.f, 0.f, 0.f, 0.f};
        #pragma unroll
        for (int c = 0; c < 4; c++) {
            const int j = j0 + c;
            const float2 z01 = unpack2(az2[c][0]), z23 = unpack2(az2[c][1]);
            const float2 p01 = unpack2(ap2[c][0]), p23 = unpack2(ap2[c][1]);
            const float zz[4] = {z01.x, z01.y, z23.x, z23.y};
            const float pp[4] = {p01.x, p01.y, p23.x, p23.y};
            const float w2j = w2s[j];
            const float bj  = b1s[j];
            float av[4];
            #pragma unroll
            for (int ss = 0; ss < 4; ss++) {
                float h2 = ftanh(zz[ss] + bj);
                float d2 = 1.f - h2*h2;
                float P = pp[ss];
                hvp[ss] = fmaf(-2.f*w2j, h2*d2*P*P, hvp[ss]);
                av[ss] = d2 * w2j;
            }
            *(float4*)(a_s + j*TBS + s0) = make_float4(av[0],av[1],av[2],av[3]);
        }
        asm volatile("bar.sync %0, 256;" :: "r"(gbar) : "memory");   // B3: a ready

        // ---- phase 3: U = W1^T a (f32x2) ----
        ull au2[4][2];
        #pragma unroll
        for (int c = 0; c < 4; c++) { au2[c][0]=0ull; au2[c][1]=0ull; }
        {
            const float* apnt = a_s + s0;
            #pragma unroll 2
            for (int j = 0; j < HID; j++) {
                const ulonglong2 av = *(const ulonglong2*)(apnt + j*TBS);
                const float4 wv = *(const float4*)(W1s + j*W1P + j0);
                const float* wa = (const float*)&wv;
                ull w;
                w = pack2(wa[0], wa[0]);
                au2[0][0]=fma2(w,av.x,au2[0][0]); au2[0][1]=fma2(w,av.y,au2[0][1]);
                w = pack2(wa[1], wa[1]);
                au2[1][0]=fma2(w,av.x,au2[1][0]); au2[1][1]=fma2(w,av.y,au2[1][1]);
                w = pack2(wa[2], wa[2]);
                au2[2][0]=fma2(w,av.x,au2[2][0]); au2[2][1]=fma2(w,av.y,au2[2][1]);
                w = pack2(wa[3], wa[3]);
                au2[3][0]=fma2(w,av.x,au2[3][0]); au2[3][1]=fma2(w,av.y,au2[3][1]);
            }
        }

        // ---- phase-3 epilogue (own rows): hvv += U.h1''; sbuf(f1s) = d1*U ----
        #pragma unroll
        for (int c = 0; c < 4; c++) {
            const int i = j0 + c;
            const float2 u01 = unpack2(au2[c][0]), u23 = unpack2(au2[c][1]);
            const float uu[4] = {u01.x, u01.y, u23.x, u23.y};
            const float4 fv = *(const float4*)(f1s + i*TBS + s0);
            const float4 hv = *(const float4*)(h1s + i*TBS + s0);
            const float fpp[4] = {fv.x, fv.y, fv.z, fv.w};
            const float hh4[4] = {hv.x, hv.y, hv.z, hv.w};
            float sv[4];
            #pragma unroll
            for (int ss = 0; ss < 4; ss++) {
                hvp[ss] = fmaf(uu[ss], fpp[ss], hvp[ss]);
                sv[ss]  = (1.f - hh4[ss]*hh4[ss]) * uu[ss];
            }
            *(float4*)(f1s + i*TBS + s0) = make_float4(sv[0],sv[1],sv[2],sv[3]);
        }
        // ---- warp-level hvv partial reduce over the warp's 4 jy groups ----
        #pragma unroll
        for (int ss = 0; ss < 4; ss++) {
            hvp[ss] += __shfl_xor_sync(0xffffffffu, hvp[ss], 8);
            hvp[ss] += __shfl_xor_sync(0xffffffffu, hvp[ss], 16);
        }
        if ((gtid & 31) < 8) {   // one lane per tx stores the warp partial
            #pragma unroll
            for (int ss = 0; ss < 4; ss++)
                hvp_s[wrp*HVP + s0 + ss] = hvp[ss];
        }
        asm volatile("bar.sync %0, 256;" :: "r"(gbar) : "memory");   // B4: sbuf+hvp ready

        // ---- phase 4 (warps 0-3): g = W0^T sbuf ----
        if (gtid < 128) {
            const int q  = gtid & 7;
            const int sp = gtid >> 3;
            ull acc = 0ull;
            const ull* w0dp = (const ull*)(W0d) + q;
            const float* fp = f1s + 2*sp;
            #pragma unroll 4
            for (int i = 0; i < HID; i++)
                acc = fma2(w0dp[i*8], *(const ull*)(fp + i*TBS), acc);
            float2 gv = unpack2(acc);
            gbf[(2*sp)*GBP + q]   = gv.x;
            gbf[(2*sp+1)*GBP + q] = gv.y;
        }
        asm volatile("bar.sync %0, 256;" :: "r"(gbar) : "memory");   // B5: gbf ready

        // ---- phase 5: Sherman-Morrison combine + coalesced store ----
        {
            float g[8];
            #pragma unroll
            for (int k = 0; k < 8; k++) g[k] = gbf[sf*GBP + k];
            float gg = 0.f;
            #pragma unroll
            for (int k = 0; k < 8; k++) gg = fmaf(g[k], g[k], gg);
            float hvv = 0.f;
            #pragma unroll
            for (int w = 0; w < 8; w++) hvv += hvp_s[w*HVP + sf];
            float xr[8], vr[8];
            #pragma unroll
            for (int k = 0; k < 8; k++) { xr[k] = Xs[sf*XP + k]; vr[k] = Xs[sf*XP + 8 + k]; }
            float gf = 0.f, fq = 0.f;
            #pragma unroll
            for (int q2 = 0; q2 < 8; q2++) {
                float fo = 0.f;
                #pragma unroll
                for (int k = 0; k < 8; k++) {
                    fo = fmaf(-Ds[q2*8+k], vr[k], fo);
                    fo = fmaf(-Ks[q2*8+k], xr[k], fo);
                }
                gf = fmaf(g[q2], fo, gf);
                if (q2 == qf) fq = fo;
            }
            float scale = (gf + hvv) / (1.f + gg);
            out[(base + sf)*8 + qf] = fq - g[qf]*scale;
        }
        // no trailing barrier: all next-tile hazards covered by B2/B3/B4/B5
        xb ^= 1;
    }
}

extern "C" void kernel_launch(void* const* d_in, const int* in_sizes, int n_in,
                              void* d_out, int out_size)
{
    const float* X  = (const float*)d_in[0];
    const float* Km = (const float*)d_in[1];
    const float* Dm = (const float*)d_in[2];
    const float* W0 = (const float*)d_in[3];
    const float* b0 = (const float*)d_in[4];
    const float* W1 = (const float*)d_in[5];
    const float* b1 = (const float*)d_in[6];
    const float* W2 = (const float*)d_in[7];

    cudaFuncSetAttribute(dyn_kernel, cudaFuncAttributeMaxDynamicSharedMemorySize,
                         (int)SMEM_BYTES);
    dyn_kernel<<<GRID, NTHREADS, SMEM_BYTES>>>(X, Km, Dm, W0, b0, W1, b1, W2,
                                               (float*)d_out);
}